// round 2
// baseline (speedup 1.0000x reference)
#include <cuda_runtime.h>
#include <math.h>

#define B_    2
#define T_    2048
#define D_    2048
#define H_    16
#define KVH_  4
#define HD_   128
#define NTOK  (B_*T_)

// ---------------- scratch (device globals: allocation-free) ----------------
__device__ float g_xkm[NTOK*D_];
__device__ float g_xvm[NTOK*D_];
__device__ float g_q  [NTOK*D_];
__device__ float g_k  [NTOK*KVH_*HD_];
__device__ float g_v  [NTOK*KVH_*HD_];
__device__ float g_g  [NTOK*D_];
__device__ float g_y  [NTOK*D_];
__device__ float g_o  [NTOK*D_];

// ---------------- time-shift mix ----------------
__global__ void mix_kernel(const float* __restrict__ xk, const float* __restrict__ xv,
                           const float* __restrict__ mk, const float* __restrict__ mv,
                           float* __restrict__ ok, float* __restrict__ ov)
{
    const int D4 = D_ / 4;                       // 512
    int idx = blockIdx.x * blockDim.x + threadIdx.x;   // float4 index
    int d4  = idx & (D4 - 1);
    int tok = idx >> 9;
    int t   = tok & (T_ - 1);

    float4 kc = ((const float4*)xk)[idx];
    float4 vc = ((const float4*)xv)[idx];
    float4 m1 = ((const float4*)mk)[d4];
    float4 m2 = ((const float4*)mv)[d4];
    float4 kp = make_float4(0.f,0.f,0.f,0.f);
    float4 vp = make_float4(0.f,0.f,0.f,0.f);
    if (t > 0) {
        kp = ((const float4*)xk)[idx - D4];
        vp = ((const float4*)xv)[idx - D4];
    }
    float4 r1, r2;
    r1.x = kc.x + m1.x*(kp.x-kc.x);  r1.y = kc.y + m1.y*(kp.y-kc.y);
    r1.z = kc.z + m1.z*(kp.z-kc.z);  r1.w = kc.w + m1.w*(kp.w-kc.w);
    r2.x = vc.x + m2.x*(vp.x-vc.x);  r2.y = vc.y + m2.y*(vp.y-vc.y);
    r2.z = vc.z + m2.z*(vp.z-vc.z);  r2.w = vc.w + m2.w*(vp.w-vc.w);
    ((float4*)ok)[idx] = r1;
    ((float4*)ov)[idx] = r2;
}

// ---------------- fp32 tiled GEMM: C[M,N] = A[M,K] @ B[K,N] ----------------
// 128x128 block tile, BK=16, 256 threads (8 warps in 4x2), 4x16 per thread.
__global__ void __launch_bounds__(256) sgemm_kernel(
    const float* __restrict__ A, const float* __restrict__ Bm,
    float* __restrict__ C, int M, int N, int K)
{
    __shared__ float As[16*132];
    __shared__ float Bs[16*132];

    const int tid = threadIdx.x;
    const int w  = tid >> 5, l  = tid & 31;
    const int wy = w >> 1,   wx = w & 1;     // 4 x 2 warps
    const int ly = l >> 2,   lx = l & 3;     // 8 x 4 lanes
    const int lrow = (wy << 5) + (ly << 2);  // 4 consecutive rows
    const int lcol = (wx << 6) + (lx << 2);  // + jj*16, jj=0..3
    const int rowg = blockIdx.y << 7;
    const int colg = blockIdx.x << 7;

    float acc[4][16];
#pragma unroll
    for (int i = 0; i < 4; i++)
#pragma unroll
        for (int j = 0; j < 16; j++) acc[i][j] = 0.f;

    for (int k0 = 0; k0 < K; k0 += 16) {
        // A tile 128x16 -> As (transposed, pad 132)
#pragma unroll
        for (int it = 0; it < 2; it++) {
            int f  = tid + (it << 8);
            int r  = f >> 2, c4 = f & 3;
            float4 t4 = *(const float4*)(A + (size_t)(rowg + r)*K + k0 + (c4 << 2));
            As[((c4<<2)+0)*132 + r] = t4.x;
            As[((c4<<2)+1)*132 + r] = t4.y;
            As[((c4<<2)+2)*132 + r] = t4.z;
            As[((c4<<2)+3)*132 + r] = t4.w;
        }
        // B tile 16x128 -> Bs (row-major, pad 132)
#pragma unroll
        for (int it = 0; it < 2; it++) {
            int f  = tid + (it << 8);
            int r  = f >> 5, c4 = f & 31;
            *(float4*)(Bs + r*132 + (c4 << 2)) =
                *(const float4*)(Bm + (size_t)(k0 + r)*N + colg + (c4 << 2));
        }
        __syncthreads();

#pragma unroll
        for (int kk = 0; kk < 16; kk++) {
            float4 a4 = *(const float4*)(As + kk*132 + lrow);
            float av[4] = {a4.x, a4.y, a4.z, a4.w};
#pragma unroll
            for (int jj = 0; jj < 4; jj++) {
                float4 b4 = *(const float4*)(Bs + kk*132 + lcol + (jj << 4));
#pragma unroll
                for (int i = 0; i < 4; i++) {
                    acc[i][(jj<<2)+0] += av[i]*b4.x;
                    acc[i][(jj<<2)+1] += av[i]*b4.y;
                    acc[i][(jj<<2)+2] += av[i]*b4.z;
                    acc[i][(jj<<2)+3] += av[i]*b4.w;
                }
            }
        }
        __syncthreads();
    }

#pragma unroll
    for (int i = 0; i < 4; i++) {
#pragma unroll
        for (int jj = 0; jj < 4; jj++) {
            float4 o;
            o.x = acc[i][(jj<<2)+0]; o.y = acc[i][(jj<<2)+1];
            o.z = acc[i][(jj<<2)+2]; o.w = acc[i][(jj<<2)+3];
            *(float4*)(C + (size_t)(rowg + lrow + i)*N + colg + lcol + (jj << 4)) = o;
        }
    }
}

// ---------------- per-head RMS norm (+ optional RoPE) ----------------
// one block of 128 threads per (token, head)
__global__ void norm_head_kernel(float* __restrict__ x, int heads, int do_rope)
{
    __shared__ float sbuf[4];
    __shared__ float svals[128];
    const int head = blockIdx.x % heads;
    const int tok  = blockIdx.x / heads;
    const int t    = tok % T_;
    float* p = x + (size_t)tok*heads*HD_ + head*HD_;
    const int d = threadIdx.x;

    float v  = p[d];
    float ss = v*v;
#pragma unroll
    for (int o = 16; o > 0; o >>= 1) ss += __shfl_xor_sync(0xffffffffu, ss, o);
    if ((d & 31) == 0) sbuf[d >> 5] = ss;
    __syncthreads();
    float tot = sbuf[0] + sbuf[1] + sbuf[2] + sbuf[3];
    float r   = rsqrtf(tot * (1.f/HD_) + 1e-8f);
    float vn  = v * r;

    if (do_rope) {
        svals[d] = vn;
        __syncthreads();
        int   j  = d & 63;
        float inv_freq = exp2f(-(float)j * (13.287712379549449f / 64.f)); // 10000^{-j/64}
        float ang = (float)t * inv_freq;
        float sn, cs;
        sincosf(ang, &sn, &cs);
        float partner = svals[d ^ 64];
        p[d] = (d < 64) ? (vn*cs - partner*sn) : (vn*cs + partner*sn);
    } else {
        p[d] = vn;
    }
}

// ---------------- flash attention (fp32, causal, GQA) ----------------
#define FBM 64
#define QP  132
#define SP  68
#define FLASH_SMEM_BYTES ((3*FBM*QP + FBM*SP + 3*FBM)*4)

__global__ void __launch_bounds__(256) flash_kernel(
    const float* __restrict__ q, const float* __restrict__ k,
    const float* __restrict__ v, float* __restrict__ y)
{
    extern __shared__ float sm[];
    float* Qs     = sm;
    float* Ks     = Qs + FBM*QP;
    float* Vs     = Ks + FBM*QP;
    float* Ss     = Vs + FBM*QP;
    float* row_m  = Ss + FBM*SP;
    float* row_l  = row_m + FBM;
    float* row_sc = row_l + FBM;

    const int tid = threadIdx.x;
    const int qt  = blockIdx.x;
    const int b   = blockIdx.y / H_;
    const int h   = blockIdx.y % H_;
    const int kvh = h / (H_ / KVH_);
    const int qs  = qt * FBM;
    const float scale = 0.08838834764831845f;   // 1/sqrt(128)

    // load Q tile (pre-scaled)
    const float* qg = q + ((size_t)(b*T_ + qs))*D_ + h*HD_;
    for (int f = tid; f < FBM*32; f += 256) {
        int r = f >> 5, c4 = f & 31;
        float4 t4 = *(const float4*)(qg + (size_t)r*D_ + (c4 << 2));
        t4.x *= scale; t4.y *= scale; t4.z *= scale; t4.w *= scale;
        *(float4*)(Qs + r*QP + (c4 << 2)) = t4;
    }
    if (tid < FBM) { row_m[tid] = -INFINITY; row_l[tid] = 0.f; }

    const int tq = tid >> 4, tk = tid & 15;
    float acc[4][8];
#pragma unroll
    for (int i = 0; i < 4; i++)
#pragma unroll
        for (int j = 0; j < 8; j++) acc[i][j] = 0.f;

    for (int kt = 0; kt <= qt; kt++) {
        const int ks = kt * FBM;
        const float* kg = k + ((size_t)(b*T_ + ks))*(KVH_*HD_) + kvh*HD_;
        const float* vg = v + ((size_t)(b*T_ + ks))*(KVH_*HD_) + kvh*HD_;
        __syncthreads();   // prior-iter reads of Ks/Vs/Ss done
        for (int f = tid; f < FBM*32; f += 256) {
            int r = f >> 5, c4 = f & 31;
            *(float4*)(Ks + r*QP + (c4<<2)) = *(const float4*)(kg + (size_t)r*(KVH_*HD_) + (c4<<2));
            *(float4*)(Vs + r*QP + (c4<<2)) = *(const float4*)(vg + (size_t)r*(KVH_*HD_) + (c4<<2));
        }
        __syncthreads();

        // S = (Q*scale) K^T : thread -> rows 4tq+i, cols tk+16j
        float s[4][4];
#pragma unroll
        for (int i = 0; i < 4; i++)
#pragma unroll
            for (int j = 0; j < 4; j++) s[i][j] = 0.f;

#pragma unroll 4
        for (int kk = 0; kk < HD_; kk += 4) {
            float4 qv[4], kv[4];
#pragma unroll
            for (int i = 0; i < 4; i++) qv[i] = *(const float4*)(Qs + (4*tq + i)*QP + kk);
#pragma unroll
            for (int j = 0; j < 4; j++) kv[j] = *(const float4*)(Ks + (tk + 16*j)*QP + kk);
#pragma unroll
            for (int i = 0; i < 4; i++)
#pragma unroll
                for (int j = 0; j < 4; j++)
                    s[i][j] += qv[i].x*kv[j].x + qv[i].y*kv[j].y
                             + qv[i].z*kv[j].z + qv[i].w*kv[j].w;
        }

        const bool diag = (kt == qt);
#pragma unroll
        for (int i = 0; i < 4; i++) {
            int r = 4*tq + i;
#pragma unroll
            for (int j = 0; j < 4; j++) {
                int c = tk + 16*j;
                float val = s[i][j];
                if (diag && c > r) val = -1e30f;
                Ss[r*SP + c] = val;
            }
        }
        __syncthreads();

        // online softmax per row
        if (tid < FBM) {
            const int r = tid;
            float m_old = row_m[r];
            float mx = m_old;
            for (int c = 0; c < FBM; c++) mx = fmaxf(mx, Ss[r*SP + c]);
            float sum = 0.f;
            for (int c = 0; c < FBM; c++) {
                float p = __expf(Ss[r*SP + c] - mx);
                Ss[r*SP + c] = p;
                sum += p;
            }
            float sc = __expf(m_old - mx);
            row_m[r]  = mx;
            row_l[r]  = row_l[r]*sc + sum;
            row_sc[r] = sc;
        }
        __syncthreads();

        // rescale + accumulate P@V : thread -> rows 4tq+i, cols tk+16jc
        float rs[4];
#pragma unroll
        for (int i = 0; i < 4; i++) rs[i] = row_sc[4*tq + i];
#pragma unroll
        for (int i = 0; i < 4; i++)
#pragma unroll
            for (int j = 0; j < 8; j++) acc[i][j] *= rs[i];

#pragma unroll 4
        for (int kk = 0; kk < FBM; kk++) {
            float p0 = Ss[(4*tq+0)*SP + kk];
            float p1 = Ss[(4*tq+1)*SP + kk];
            float p2 = Ss[(4*tq+2)*SP + kk];
            float p3 = Ss[(4*tq+3)*SP + kk];
#pragma unroll
            for (int j = 0; j < 8; j++) {
                float vv = Vs[kk*QP + tk + 16*j];
                acc[0][j] += p0*vv;
                acc[1][j] += p1*vv;
                acc[2][j] += p2*vv;
                acc[3][j] += p3*vv;
            }
        }
    }
    __syncthreads();

    float* yg = y + ((size_t)(b*T_ + qs))*D_ + h*HD_;
#pragma unroll
    for (int i = 0; i < 4; i++) {
        int r = 4*tq + i;
        float inv = 1.f / row_l[r];
#pragma unroll
        for (int j = 0; j < 8; j++)
            yg[(size_t)r*D_ + tk + 16*j] = acc[i][j] * inv;
    }
}

// ---------------- L2 norm per head + gate ----------------
__global__ void gate_l2_kernel(float* __restrict__ y, const float* __restrict__ g)
{
    __shared__ float sbuf[4];
    const int head = blockIdx.x % H_;
    const int tok  = blockIdx.x / H_;
    float*       yp = y + (size_t)tok*D_ + head*HD_;
    const float* gp = g + (size_t)tok*D_ + head*HD_;
    const int d = threadIdx.x;

    float v  = yp[d];
    float ss = v*v;
#pragma unroll
    for (int o = 16; o > 0; o >>= 1) ss += __shfl_xor_sync(0xffffffffu, ss, o);
    if ((d & 31) == 0) sbuf[d >> 5] = ss;
    __syncthreads();
    float tot = sbuf[0] + sbuf[1] + sbuf[2] + sbuf[3];
    float n   = sqrtf(tot);
    yp[d] = gp[d] * v / fmaxf(n, 1e-12f);
}

// ---------------- final RMS norm over D, scaled by 1/sqrt(48) ----------------
__global__ void final_norm_kernel(const float* __restrict__ in, float* __restrict__ out)
{
    __shared__ float sbuf[8];
    const int tok = blockIdx.x;
    const float* p = in + (size_t)tok*D_;
    const int base = threadIdx.x * 8;

    float4 a = *(const float4*)(p + base);
    float4 b = *(const float4*)(p + base + 4);
    float ss = a.x*a.x + a.y*a.y + a.z*a.z + a.w*a.w
             + b.x*b.x + b.y*b.y + b.z*b.z + b.w*b.w;
#pragma unroll
    for (int o = 16; o > 0; o >>= 1) ss += __shfl_xor_sync(0xffffffffu, ss, o);
    if ((threadIdx.x & 31) == 0) sbuf[threadIdx.x >> 5] = ss;
    __syncthreads();
    float tot = 0.f;
#pragma unroll
    for (int i = 0; i < 8; i++) tot += sbuf[i];
    float r = rsqrtf(tot * (1.f/D_) + 1e-8f) * 0.14433756729740643f; // 1/sqrt(48)

    float* q = out + (size_t)tok*D_;
    a.x*=r; a.y*=r; a.z*=r; a.w*=r;
    b.x*=r; b.y*=r; b.z*=r; b.w*=r;
    *(float4*)(q + base)     = a;
    *(float4*)(q + base + 4) = b;
}

// ---------------- launcher ----------------
extern "C" void kernel_launch(void* const* d_in, const int* in_sizes, int n_in,
                              void* d_out, int out_size)
{
    (void)in_sizes; (void)n_in; (void)out_size;
    const float* xq = (const float*)d_in[0];
    const float* xk = (const float*)d_in[1];
    const float* xv = (const float*)d_in[2];
    const float* Wq = (const float*)d_in[3];
    const float* Wk = (const float*)d_in[4];
    const float* Wv = (const float*)d_in[5];
    const float* Wg = (const float*)d_in[6];
    const float* Wo = (const float*)d_in[7];
    const float* mk = (const float*)d_in[8];
    const float* mv = (const float*)d_in[9];
    float* out = (float*)d_out;

    float *pxkm, *pxvm, *pq, *pk, *pv, *pg, *py, *po;
    cudaGetSymbolAddress((void**)&pxkm, g_xkm);
    cudaGetSymbolAddress((void**)&pxvm, g_xvm);
    cudaGetSymbolAddress((void**)&pq,   g_q);
    cudaGetSymbolAddress((void**)&pk,   g_k);
    cudaGetSymbolAddress((void**)&pv,   g_v);
    cudaGetSymbolAddress((void**)&pg,   g_g);
    cudaGetSymbolAddress((void**)&py,   g_y);
    cudaGetSymbolAddress((void**)&po,   g_o);

    cudaFuncSetAttribute(flash_kernel, cudaFuncAttributeMaxDynamicSharedMemorySize,
                         FLASH_SMEM_BYTES);

    // 1) time-shift mix for k/v paths
    mix_kernel<<<(NTOK*D_/4)/256, 256>>>(xk, xv, mk, mv, pxkm, pxvm);

    // 2) projections
    sgemm_kernel<<<dim3(D_/128,  NTOK/128), 256>>>(xq,   Wq, pq, NTOK, D_,  D_);
    sgemm_kernel<<<dim3(512/128, NTOK/128), 256>>>(pxkm, Wk, pk, NTOK, 512, D_);
    sgemm_kernel<<<dim3(512/128, NTOK/128), 256>>>(pxvm, Wv, pv, NTOK, 512, D_);
    sgemm_kernel<<<dim3(D_/128,  NTOK/128), 256>>>(xq,   Wg, pg, NTOK, D_,  D_);

    // 3) per-head RMS norm (+RoPE for q,k)
    norm_head_kernel<<<NTOK*H_,   128>>>(pq, H_,   1);
    norm_head_kernel<<<NTOK*KVH_, 128>>>(pk, KVH_, 1);
    norm_head_kernel<<<NTOK*KVH_, 128>>>(pv, KVH_, 0);

    // 4) causal GQA attention
    flash_kernel<<<dim3(T_/FBM, B_*H_), 256, FLASH_SMEM_BYTES>>>(pq, pk, pv, py);

    // 5) per-head L2 norm + gate
    gate_l2_kernel<<<NTOK*H_, 128>>>(py, pg);

    // 6) output projection
    sgemm_kernel<<<dim3(D_/128, NTOK/128), 256>>>(py, Wo, po, NTOK, D_, D_);

    // 7) final RMS norm + 1/sqrt(2*N_LAYER)
    final_norm_kernel<<<NTOK, 256>>>(po, out);
}

// round 5
// speedup vs baseline: 1.8644x; 1.8644x over previous
#include <cuda_runtime.h>
#include <cuda_bf16.h>
#include <math.h>
#include <stdint.h>

#define B_    2
#define T_    2048
#define D_    2048
#define H_    16
#define KVH_  4
#define HD_   128
#define NTOK  (B_*T_)

// ---------------- scratch (device globals: allocation-free) ----------------
__device__ float g_xkm[NTOK*D_];
__device__ float g_xvm[NTOK*D_];
__device__ float g_q  [NTOK*D_];
__device__ float g_k  [NTOK*KVH_*HD_];
__device__ float g_v  [NTOK*KVH_*HD_];
__device__ float g_g  [NTOK*D_];
__device__ float g_y  [NTOK*D_];
__device__ float g_o  [NTOK*D_];
// split-bf16 operands
__device__ __align__(16) __nv_bfloat16 g_ah [NTOK*D_];
__device__ __align__(16) __nv_bfloat16 g_al [NTOK*D_];
__device__ __align__(16) __nv_bfloat16 g_wth[D_*D_];
__device__ __align__(16) __nv_bfloat16 g_wtl[D_*D_];

// ================= baseline-ISA helpers (no tcgen05 / no 'a' features) =====
__device__ __forceinline__ uint32_t smem_u32(const void* p) {
    uint32_t a;
    asm("{ .reg .u64 t; cvta.to.shared.u64 t, %1; cvt.u32.u64 %0, t; }" : "=r"(a) : "l"(p));
    return a;
}
__device__ __forceinline__ uint32_t sw128(uint32_t off) { return off ^ ((off >> 3) & 0x70); }

__device__ __forceinline__ void cp_async16(uint32_t dst, const void* src) {
    asm volatile("cp.async.cg.shared.global [%0], [%1], 16;" :: "r"(dst), "l"(src) : "memory");
}
#define CP_COMMIT() asm volatile("cp.async.commit_group;" ::: "memory")
#define CP_WAIT(n)  asm volatile("cp.async.wait_group %0;" :: "n"(n) : "memory")

__device__ __forceinline__ void ldsm_x4(uint32_t* r, uint32_t addr) {
    asm volatile("ldmatrix.sync.aligned.m8n8.x4.shared.b16 {%0,%1,%2,%3}, [%4];"
                 : "=r"(r[0]), "=r"(r[1]), "=r"(r[2]), "=r"(r[3]) : "r"(addr));
}
__device__ __forceinline__ void ldsm_x2(uint32_t* r, uint32_t addr) {
    asm volatile("ldmatrix.sync.aligned.m8n8.x2.shared.b16 {%0,%1}, [%2];"
                 : "=r"(r[0]), "=r"(r[1]) : "r"(addr));
}
__device__ __forceinline__ void mma16816(float* d, const uint32_t* a, const uint32_t* b) {
    asm volatile("mma.sync.aligned.m16n8k16.row.col.f32.bf16.bf16.f32 "
                 "{%0,%1,%2,%3}, {%4,%5,%6,%7}, {%8,%9}, {%0,%1,%2,%3};"
                 : "+f"(d[0]), "+f"(d[1]), "+f"(d[2]), "+f"(d[3])
                 : "r"(a[0]), "r"(a[1]), "r"(a[2]), "r"(a[3]), "r"(b[0]), "r"(b[1]));
}

// ================= split / transpose conversions =================
__global__ void split_x_kernel(const float* __restrict__ x,
                               __nv_bfloat16* __restrict__ hi,
                               __nv_bfloat16* __restrict__ lo)
{
    int i = blockIdx.x * blockDim.x + threadIdx.x;   // float4 index
    float4 v = ((const float4*)x)[i];
    __nv_bfloat16 h0 = __float2bfloat16(v.x), h1 = __float2bfloat16(v.y);
    __nv_bfloat16 h2 = __float2bfloat16(v.z), h3 = __float2bfloat16(v.w);
    __nv_bfloat16 l0 = __float2bfloat16(v.x - __bfloat162float(h0));
    __nv_bfloat16 l1 = __float2bfloat16(v.y - __bfloat162float(h1));
    __nv_bfloat16 l2 = __float2bfloat16(v.z - __bfloat162float(h2));
    __nv_bfloat16 l3 = __float2bfloat16(v.w - __bfloat162float(h3));
    __nv_bfloat162* H = (__nv_bfloat162*)hi;
    __nv_bfloat162* L = (__nv_bfloat162*)lo;
    H[2*i]   = __nv_bfloat162(h0, h1);
    H[2*i+1] = __nv_bfloat162(h2, h3);
    L[2*i]   = __nv_bfloat162(l0, l1);
    L[2*i+1] = __nv_bfloat162(l2, l3);
}

// W[K=2048, N] -> Wt_hi/lo [N, 2048] (transposed, split)
__global__ void wsplit_t_kernel(const float* __restrict__ W,
                                __nv_bfloat16* __restrict__ th,
                                __nv_bfloat16* __restrict__ tl, int N)
{
    __shared__ float s[32][33];
    const int k0 = blockIdx.y * 32, n0 = blockIdx.x * 32;
    const int tx = threadIdx.x, ty = threadIdx.y;
    s[ty][tx] = W[(size_t)(k0 + ty) * N + n0 + tx];
    __syncthreads();
    float v = s[tx][ty];   // = W[k0+tx][n0+ty]
    __nv_bfloat16 h = __float2bfloat16(v);
    __nv_bfloat16 l = __float2bfloat16(v - __bfloat162float(h));
    size_t o = (size_t)(n0 + ty) * D_ + k0 + tx;
    th[o] = h;
    tl[o] = l;
}

// ================= split-bf16 GEMM via mma.sync (HMMA) =================
// C[M,N] = A[M,2048] @ W[2048,N]; A as ah+al [M,K] bf16, W as wth+wtl [N,K].
// Block 128x128, BK=64, 256 threads; warp tile 32(M) x 64(N).
#define GK        2048
#define NCH       (GK/64)
#define TILEB     16384          /* 128 rows x 128B */
#define STAGEB    (4*TILEB)
#define GEMM_SMEM (2*STAGEB + 1024)

__global__ void __launch_bounds__(256, 1) gemm_mma_kernel(
    const __nv_bfloat16* __restrict__ ah, const __nv_bfloat16* __restrict__ al,
    const __nv_bfloat16* __restrict__ wth, const __nv_bfloat16* __restrict__ wtl,
    float* __restrict__ C, int N)
{
    extern __shared__ char sm[];
    const uint32_t smb   = smem_u32(sm);
    const uint32_t tiles = (smb + 1023u) & ~1023u;

    const int tid  = threadIdx.x;
    const int wid  = tid >> 5, lane = tid & 31;
    const int wm   = wid & 3,  wn   = wid >> 2;
    const int m0   = blockIdx.y << 7;
    const int n0   = blockIdx.x << 7;

    const __nv_bfloat16* srcs[4] = { ah  + (size_t)m0 * GK, al  + (size_t)m0 * GK,
                                     wth + (size_t)n0 * GK, wtl + (size_t)n0 * GK };

    float acc[2][8][4];
#pragma unroll
    for (int i = 0; i < 2; i++)
#pragma unroll
        for (int j = 0; j < 8; j++)
#pragma unroll
            for (int q = 0; q < 4; q++) acc[i][j][q] = 0.f;

    // ---- async prefetch of one 64-wide K chunk (4 tiles) into a stage ----
    auto prefetch = [&](int ch) {
        const uint32_t stage = tiles + (uint32_t)(ch & 1) * STAGEB;
        const int ke = ch << 6;
#pragma unroll
        for (int t = 0; t < 4; t++) {
            const __nv_bfloat16* s = srcs[t];
#pragma unroll
            for (int j = 0; j < 4; j++) {
                int idx = tid + (j << 8);      // 0..1023
                int r   = idx >> 3;            // row 0..127
                int c   = idx & 7;             // 16B seg 0..7
                cp_async16(stage + t * TILEB + sw128((r << 7) + (c << 4)),
                           s + (size_t)r * GK + ke + (c << 3));
            }
        }
        CP_COMMIT();
    };

    prefetch(0);

    for (int ch = 0; ch < NCH; ch++) {
        if (ch + 1 < NCH) { prefetch(ch + 1); CP_WAIT(1); }
        else              { CP_WAIT(0); }
        __syncthreads();

        const uint32_t stage = tiles + (uint32_t)(ch & 1) * STAGEB;
        const uint32_t sAh = stage,            sAl = stage + TILEB;
        const uint32_t sBh = stage + 2*TILEB,  sBl = stage + 3*TILEB;

#pragma unroll
        for (int ks = 0; ks < 4; ks++) {
            const int kb = ks << 5;   // 32B per k16 step

            uint32_t ahf[2][4], alf[2][4];
#pragma unroll
            for (int mt = 0; mt < 2; mt++) {
                int row = wm*32 + mt*16 + (lane & 15);
                uint32_t off = sw128((uint32_t)(row << 7) + kb + ((lane >> 4) << 4));
                ldsm_x4(ahf[mt], sAh + off);
                ldsm_x4(alf[mt], sAl + off);
            }
            uint32_t bhf[8][2], blf[8][2];
            const int brow = wn*64 + (lane & 7);
            const int bko  = kb + (((lane >> 3) & 1) << 4);
#pragma unroll
            for (int nt = 0; nt < 8; nt++) {
                uint32_t off = sw128((uint32_t)((brow + nt*8) << 7) + bko);
                ldsm_x2(bhf[nt], sBh + off);
                ldsm_x2(blf[nt], sBl + off);
            }
#pragma unroll
            for (int mt = 0; mt < 2; mt++)
#pragma unroll
                for (int nt = 0; nt < 8; nt++) {
                    mma16816(acc[mt][nt], ahf[mt], bhf[nt]);
                    mma16816(acc[mt][nt], ahf[mt], blf[nt]);
                    mma16816(acc[mt][nt], alf[mt], bhf[nt]);
                }
        }
        __syncthreads();
    }

    // ---- epilogue: direct fp32 stores ----
    const int er = lane >> 2, ec = (lane & 3) << 1;
#pragma unroll
    for (int mt = 0; mt < 2; mt++) {
        int r0 = m0 + wm*32 + mt*16 + er;
#pragma unroll
        for (int nt = 0; nt < 8; nt++) {
            int c = n0 + wn*64 + nt*8 + ec;
            *(float2*)(C + (size_t)r0      * N + c) = make_float2(acc[mt][nt][0], acc[mt][nt][1]);
            *(float2*)(C + (size_t)(r0 + 8)* N + c) = make_float2(acc[mt][nt][2], acc[mt][nt][3]);
        }
    }
}

// ---------------- time-shift mix ----------------
__global__ void mix_kernel(const float* __restrict__ xk, const float* __restrict__ xv,
                           const float* __restrict__ mk, const float* __restrict__ mv,
                           float* __restrict__ ok, float* __restrict__ ov)
{
    const int D4 = D_ / 4;
    int idx = blockIdx.x * blockDim.x + threadIdx.x;
    int d4  = idx & (D4 - 1);
    int tok = idx >> 9;
    int t   = tok & (T_ - 1);

    float4 kc = ((const float4*)xk)[idx];
    float4 vc = ((const float4*)xv)[idx];
    float4 m1 = ((const float4*)mk)[d4];
    float4 m2 = ((const float4*)mv)[d4];
    float4 kp = make_float4(0.f,0.f,0.f,0.f);
    float4 vp = make_float4(0.f,0.f,0.f,0.f);
    if (t > 0) {
        kp = ((const float4*)xk)[idx - D4];
        vp = ((const float4*)xv)[idx - D4];
    }
    float4 r1, r2;
    r1.x = kc.x + m1.x*(kp.x-kc.x);  r1.y = kc.y + m1.y*(kp.y-kc.y);
    r1.z = kc.z + m1.z*(kp.z-kc.z);  r1.w = kc.w + m1.w*(kp.w-kc.w);
    r2.x = vc.x + m2.x*(vp.x-vc.x);  r2.y = vc.y + m2.y*(vp.y-vc.y);
    r2.z = vc.z + m2.z*(vp.z-vc.z);  r2.w = vc.w + m2.w*(vp.w-vc.w);
    ((float4*)ok)[idx] = r1;
    ((float4*)ov)[idx] = r2;
}

// ---------------- per-head RMS norm (+ optional RoPE) ----------------
__global__ void norm_head_kernel(float* __restrict__ x, int heads, int do_rope)
{
    __shared__ float sbuf[4];
    __shared__ float svals[128];
    const int head = blockIdx.x % heads;
    const int tok  = blockIdx.x / heads;
    const int t    = tok % T_;
    float* p = x + (size_t)tok*heads*HD_ + head*HD_;
    const int d = threadIdx.x;

    float v  = p[d];
    float ss = v*v;
#pragma unroll
    for (int o = 16; o > 0; o >>= 1) ss += __shfl_xor_sync(0xffffffffu, ss, o);
    if ((d & 31) == 0) sbuf[d >> 5] = ss;
    __syncthreads();
    float tot = sbuf[0] + sbuf[1] + sbuf[2] + sbuf[3];
    float r   = rsqrtf(tot * (1.f/HD_) + 1e-8f);
    float vn  = v * r;

    if (do_rope) {
        svals[d] = vn;
        __syncthreads();
        int   j  = d & 63;
        float inv_freq = exp2f(-(float)j * (13.287712379549449f / 64.f));
        float ang = (float)t * inv_freq;
        float sn, cs;
        sincosf(ang, &sn, &cs);
        float partner = svals[d ^ 64];
        p[d] = (d < 64) ? (vn*cs - partner*sn) : (vn*cs + partner*sn);
    } else {
        p[d] = vn;
    }
}

// ---------------- flash attention (fp32, causal, GQA) ----------------
#define FBM 64
#define QP  132
#define SP  68
#define FLASH_SMEM_BYTES ((3*FBM*QP + FBM*SP + 3*FBM)*4)

__global__ void __launch_bounds__(256) flash_kernel(
    const float* __restrict__ q, const float* __restrict__ k,
    const float* __restrict__ v, float* __restrict__ y)
{
    extern __shared__ float smf[];
    float* Qs     = smf;
    float* Ks     = Qs + FBM*QP;
    float* Vs     = Ks + FBM*QP;
    float* Ss     = Vs + FBM*QP;
    float* row_m  = Ss + FBM*SP;
    float* row_l  = row_m + FBM;
    float* row_sc = row_l + FBM;

    const int tid = threadIdx.x;
    const int qt  = blockIdx.x;
    const int b   = blockIdx.y / H_;
    const int h   = blockIdx.y % H_;
    const int kvh = h / (H_ / KVH_);
    const int qs  = qt * FBM;
    const float scale = 0.08838834764831845f;

    const float* qg = q + ((size_t)(b*T_ + qs))*D_ + h*HD_;
    for (int f = tid; f < FBM*32; f += 256) {
        int r = f >> 5, c4 = f & 31;
        float4 t4 = *(const float4*)(qg + (size_t)r*D_ + (c4 << 2));
        t4.x *= scale; t4.y *= scale; t4.z *= scale; t4.w *= scale;
        *(float4*)(Qs + r*QP + (c4 << 2)) = t4;
    }
    if (tid < FBM) { row_m[tid] = -INFINITY; row_l[tid] = 0.f; }

    const int tq = tid >> 4, tk = tid & 15;
    float acc[4][8];
#pragma unroll
    for (int i = 0; i < 4; i++)
#pragma unroll
        for (int j = 0; j < 8; j++) acc[i][j] = 0.f;

    for (int kt = 0; kt <= qt; kt++) {
        const int ks = kt * FBM;
        const float* kg = k + ((size_t)(b*T_ + ks))*(KVH_*HD_) + kvh*HD_;
        const float* vg = v + ((size_t)(b*T_ + ks))*(KVH_*HD_) + kvh*HD_;
        __syncthreads();
        for (int f = tid; f < FBM*32; f += 256) {
            int r = f >> 5, c4 = f & 31;
            *(float4*)(Ks + r*QP + (c4<<2)) = *(const float4*)(kg + (size_t)r*(KVH_*HD_) + (c4<<2));
            *(float4*)(Vs + r*QP + (c4<<2)) = *(const float4*)(vg + (size_t)r*(KVH_*HD_) + (c4<<2));
        }
        __syncthreads();

        float s[4][4];
#pragma unroll
        for (int i = 0; i < 4; i++)
#pragma unroll
            for (int j = 0; j < 4; j++) s[i][j] = 0.f;

#pragma unroll 4
        for (int kk = 0; kk < HD_; kk += 4) {
            float4 qv[4], kv[4];
#pragma unroll
            for (int i = 0; i < 4; i++) qv[i] = *(const float4*)(Qs + (4*tq + i)*QP + kk);
#pragma unroll
            for (int j = 0; j < 4; j++) kv[j] = *(const float4*)(Ks + (tk + 16*j)*QP + kk);
#pragma unroll
            for (int i = 0; i < 4; i++)
#pragma unroll
                for (int j = 0; j < 4; j++)
                    s[i][j] += qv[i].x*kv[j].x + qv[i].y*kv[j].y
                             + qv[i].z*kv[j].z + qv[i].w*kv[j].w;
        }

        const bool diag = (kt == qt);
#pragma unroll
        for (int i = 0; i < 4; i++) {
            int r = 4*tq + i;
#pragma unroll
            for (int j = 0; j < 4; j++) {
                int c = tk + 16*j;
                float val = s[i][j];
                if (diag && c > r) val = -1e30f;
                Ss[r*SP + c] = val;
            }
        }
        __syncthreads();

        // online softmax: 4 threads per row
        {
            const int r = tid >> 2, sub = tid & 3;
            float m_old = row_m[r];
            float mx = m_old;
#pragma unroll
            for (int c0 = 0; c0 < 16; c0++)
                mx = fmaxf(mx, Ss[r*SP + sub*16 + c0]);
            mx = fmaxf(mx, __shfl_xor_sync(0xffffffffu, mx, 1));
            mx = fmaxf(mx, __shfl_xor_sync(0xffffffffu, mx, 2));
            float sum = 0.f;
#pragma unroll
            for (int c0 = 0; c0 < 16; c0++) {
                int c = sub*16 + c0;
                float p = __expf(Ss[r*SP + c] - mx);
                Ss[r*SP + c] = p;
                sum += p;
            }
            sum += __shfl_xor_sync(0xffffffffu, sum, 1);
            sum += __shfl_xor_sync(0xffffffffu, sum, 2);
            if (sub == 0) {
                float sc = __expf(m_old - mx);
                row_m[r]  = mx;
                row_l[r]  = row_l[r]*sc + sum;
                row_sc[r] = sc;
            }
        }
        __syncthreads();

        float rs[4];
#pragma unroll
        for (int i = 0; i < 4; i++) rs[i] = row_sc[4*tq + i];
#pragma unroll
        for (int i = 0; i < 4; i++)
#pragma unroll
            for (int j = 0; j < 8; j++) acc[i][j] *= rs[i];

#pragma unroll 4
        for (int kk = 0; kk < FBM; kk++) {
            float p0 = Ss[(4*tq+0)*SP + kk];
            float p1 = Ss[(4*tq+1)*SP + kk];
            float p2 = Ss[(4*tq+2)*SP + kk];
            float p3 = Ss[(4*tq+3)*SP + kk];
#pragma unroll
            for (int j = 0; j < 8; j++) {
                float vv = Vs[kk*QP + tk + 16*j];
                acc[0][j] += p0*vv;
                acc[1][j] += p1*vv;
                acc[2][j] += p2*vv;
                acc[3][j] += p3*vv;
            }
        }
    }
    __syncthreads();

    float* yg = y + ((size_t)(b*T_ + qs))*D_ + h*HD_;
#pragma unroll
    for (int i = 0; i < 4; i++) {
        int r = 4*tq + i;
        float inv = 1.f / row_l[r];
#pragma unroll
        for (int j = 0; j < 8; j++)
            yg[(size_t)r*D_ + tk + 16*j] = acc[i][j] * inv;
    }
}

// ---------------- L2 norm per head + gate ----------------
__global__ void gate_l2_kernel(float* __restrict__ y, const float* __restrict__ g)
{
    __shared__ float sbuf[4];
    const int head = blockIdx.x % H_;
    const int tok  = blockIdx.x / H_;
    float*       yp = y + (size_t)tok*D_ + head*HD_;
    const float* gp = g + (size_t)tok*D_ + head*HD_;
    const int d = threadIdx.x;

    float v  = yp[d];
    float ss = v*v;
#pragma unroll
    for (int o = 16; o > 0; o >>= 1) ss += __shfl_xor_sync(0xffffffffu, ss, o);
    if ((d & 31) == 0) sbuf[d >> 5] = ss;
    __syncthreads();
    float tot = sbuf[0] + sbuf[1] + sbuf[2] + sbuf[3];
    float n   = sqrtf(tot);
    yp[d] = gp[d] * v / fmaxf(n, 1e-12f);
}

// ---------------- final RMS norm over D, scaled by 1/sqrt(48) ----------------
__global__ void final_norm_kernel(const float* __restrict__ in, float* __restrict__ out)
{
    __shared__ float sbuf[8];
    const int tok = blockIdx.x;
    const float* p = in + (size_t)tok*D_;
    const int base = threadIdx.x * 8;

    float4 a = *(const float4*)(p + base);
    float4 b = *(const float4*)(p + base + 4);
    float ss = a.x*a.x + a.y*a.y + a.z*a.z + a.w*a.w
             + b.x*b.x + b.y*b.y + b.z*b.z + b.w*b.w;
#pragma unroll
    for (int o = 16; o > 0; o >>= 1) ss += __shfl_xor_sync(0xffffffffu, ss, o);
    if ((threadIdx.x & 31) == 0) sbuf[threadIdx.x >> 5] = ss;
    __syncthreads();
    float tot = 0.f;
#pragma unroll
    for (int i = 0; i < 8; i++) tot += sbuf[i];
    float r = rsqrtf(tot * (1.f/D_) + 1e-8f) * 0.14433756729740643f;

    float* q = out + (size_t)tok*D_;
    a.x*=r; a.y*=r; a.z*=r; a.w*=r;
    b.x*=r; b.y*=r; b.z*=r; b.w*=r;
    *(float4*)(q + base)     = a;
    *(float4*)(q + base + 4) = b;
}

// ---------------- launcher ----------------
extern "C" void kernel_launch(void* const* d_in, const int* in_sizes, int n_in,
                              void* d_out, int out_size)
{
    (void)in_sizes; (void)n_in; (void)out_size;
    const float* xq = (const float*)d_in[0];
    const float* xk = (const float*)d_in[1];
    const float* xv = (const float*)d_in[2];
    const float* Wq = (const float*)d_in[3];
    const float* Wk = (const float*)d_in[4];
    const float* Wv = (const float*)d_in[5];
    const float* Wg = (const float*)d_in[6];
    const float* Wo = (const float*)d_in[7];
    const float* mk = (const float*)d_in[8];
    const float* mv = (const float*)d_in[9];
    float* out = (float*)d_out;

    float *pxkm, *pxvm, *pq, *pk, *pv, *pg, *py, *po;
    __nv_bfloat16 *pah, *pal, *pwth, *pwtl;
    cudaGetSymbolAddress((void**)&pxkm, g_xkm);
    cudaGetSymbolAddress((void**)&pxvm, g_xvm);
    cudaGetSymbolAddress((void**)&pq,   g_q);
    cudaGetSymbolAddress((void**)&pk,   g_k);
    cudaGetSymbolAddress((void**)&pv,   g_v);
    cudaGetSymbolAddress((void**)&pg,   g_g);
    cudaGetSymbolAddress((void**)&py,   g_y);
    cudaGetSymbolAddress((void**)&po,   g_o);
    cudaGetSymbolAddress((void**)&pah,  g_ah);
    cudaGetSymbolAddress((void**)&pal,  g_al);
    cudaGetSymbolAddress((void**)&pwth, g_wth);
    cudaGetSymbolAddress((void**)&pwtl, g_wtl);

    cudaFuncSetAttribute(flash_kernel, cudaFuncAttributeMaxDynamicSharedMemorySize,
                         FLASH_SMEM_BYTES);
    cudaFuncSetAttribute(gemm_mma_kernel, cudaFuncAttributeMaxDynamicSharedMemorySize,
                         GEMM_SMEM);

    const int XS_GRID = (NTOK*D_/4)/256;
    dim3 wgrid_full(D_/32, D_/32), wgrid_kv(512/32, D_/32), wblk(32, 32);

    // 1) time-shift mix for k/v paths
    mix_kernel<<<XS_GRID, 256>>>(xk, xv, mk, mv, pxkm, pxvm);

    // 2) q-side projections (xq -> Wq, Wg)
    split_x_kernel<<<XS_GRID, 256>>>(xq, pah, pal);
    wsplit_t_kernel<<<wgrid_full, wblk>>>(Wq, pwth, pwtl, D_);
    gemm_mma_kernel<<<dim3(D_/128, NTOK/128), 256, GEMM_SMEM>>>(pah, pal, pwth, pwtl, pq, D_);
    wsplit_t_kernel<<<wgrid_full, wblk>>>(Wg, pwth, pwtl, D_);
    gemm_mma_kernel<<<dim3(D_/128, NTOK/128), 256, GEMM_SMEM>>>(pah, pal, pwth, pwtl, pg, D_);

    // 3) k/v projections
    split_x_kernel<<<XS_GRID, 256>>>(pxkm, pah, pal);
    wsplit_t_kernel<<<wgrid_kv, wblk>>>(Wk, pwth, pwtl, 512);
    gemm_mma_kernel<<<dim3(512/128, NTOK/128), 256, GEMM_SMEM>>>(pah, pal, pwth, pwtl, pk, 512);
    split_x_kernel<<<XS_GRID, 256>>>(pxvm, pah, pal);
    wsplit_t_kernel<<<wgrid_kv, wblk>>>(Wv, pwth, pwtl, 512);
    gemm_mma_kernel<<<dim3(512/128, NTOK/128), 256, GEMM_SMEM>>>(pah, pal, pwth, pwtl, pv, 512);

    // 4) per-head RMS norm (+RoPE for q,k)
    norm_head_kernel<<<NTOK*H_,   128>>>(pq, H_,   1);
    norm_head_kernel<<<NTOK*KVH_, 128>>>(pk, KVH_, 1);
    norm_head_kernel<<<NTOK*KVH_, 128>>>(pv, KVH_, 0);

    // 5) causal GQA attention
    flash_kernel<<<dim3(T_/FBM, B_*H_), 256, FLASH_SMEM_BYTES>>>(pq, pk, pv, py);

    // 6) per-head L2 norm + gate
    gate_l2_kernel<<<NTOK*H_, 128>>>(py, pg);

    // 7) output projection
    split_x_kernel<<<XS_GRID, 256>>>(py, pah, pal);
    wsplit_t_kernel<<<wgrid_full, wblk>>>(Wo, pwth, pwtl, D_);
    gemm_mma_kernel<<<dim3(D_/128, NTOK/128), 256, GEMM_SMEM>>>(pah, pal, pwth, pwtl, po, D_);

    // 8) final RMS norm + 1/sqrt(2*N_LAYER)
    final_norm_kernel<<<NTOK, 256>>>(po, out);
}

// round 6
// speedup vs baseline: 2.7410x; 1.4702x over previous
#include <cuda_runtime.h>
#include <cuda_bf16.h>
#include <math.h>
#include <stdint.h>

#define B_    2
#define T_    2048
#define D_    2048
#define H_    16
#define KVH_  4
#define HD_   128
#define NTOK  (B_*T_)

// ---------------- scratch (device globals: allocation-free) ----------------
__device__ float g_xkm[NTOK*D_];
__device__ float g_xvm[NTOK*D_];
__device__ float g_q  [NTOK*D_];
__device__ float g_k  [NTOK*KVH_*HD_];
__device__ float g_v  [NTOK*KVH_*HD_];
__device__ float g_g  [NTOK*D_];
__device__ float g_y  [NTOK*D_];
__device__ float g_o  [NTOK*D_];
// split-bf16 operands
__device__ __align__(16) __nv_bfloat16 g_ah [NTOK*D_];
__device__ __align__(16) __nv_bfloat16 g_al [NTOK*D_];
__device__ __align__(16) __nv_bfloat16 g_wth[D_*D_];
__device__ __align__(16) __nv_bfloat16 g_wtl[D_*D_];

// ================= baseline-ISA helpers =================
__device__ __forceinline__ uint32_t smem_u32(const void* p) {
    uint32_t a;
    asm("{ .reg .u64 t; cvta.to.shared.u64 t, %1; cvt.u32.u64 %0, t; }" : "=r"(a) : "l"(p));
    return a;
}
__device__ __forceinline__ uint32_t sw128(uint32_t off) { return off ^ ((off >> 3) & 0x70); }
// swizzle for 256B rows: bits[6:4] ^= bits[10:8]
__device__ __forceinline__ uint32_t sw256(uint32_t off) { return off ^ ((off >> 4) & 0x70); }

__device__ __forceinline__ void cp_async16(uint32_t dst, const void* src) {
    asm volatile("cp.async.cg.shared.global [%0], [%1], 16;" :: "r"(dst), "l"(src) : "memory");
}
#define CP_COMMIT() asm volatile("cp.async.commit_group;" ::: "memory")
#define CP_WAIT(n)  asm volatile("cp.async.wait_group %0;" :: "n"(n) : "memory")

__device__ __forceinline__ void ldsm_x4(uint32_t* r, uint32_t addr) {
    asm volatile("ldmatrix.sync.aligned.m8n8.x4.shared.b16 {%0,%1,%2,%3}, [%4];"
                 : "=r"(r[0]), "=r"(r[1]), "=r"(r[2]), "=r"(r[3]) : "r"(addr));
}
__device__ __forceinline__ void ldsm_x2(uint32_t* r, uint32_t addr) {
    asm volatile("ldmatrix.sync.aligned.m8n8.x2.shared.b16 {%0,%1}, [%2];"
                 : "=r"(r[0]), "=r"(r[1]) : "r"(addr));
}
__device__ __forceinline__ void ldsm_x2_t(uint32_t* r, uint32_t addr) {
    asm volatile("ldmatrix.sync.aligned.m8n8.x2.trans.shared.b16 {%0,%1}, [%2];"
                 : "=r"(r[0]), "=r"(r[1]) : "r"(addr));
}
__device__ __forceinline__ void mma16816(float* d, const uint32_t* a, const uint32_t* b) {
    asm volatile("mma.sync.aligned.m16n8k16.row.col.f32.bf16.bf16.f32 "
                 "{%0,%1,%2,%3}, {%4,%5,%6,%7}, {%8,%9}, {%0,%1,%2,%3};"
                 : "+f"(d[0]), "+f"(d[1]), "+f"(d[2]), "+f"(d[3])
                 : "r"(a[0]), "r"(a[1]), "r"(a[2]), "r"(a[3]), "r"(b[0]), "r"(b[1]));
}

// fast exp on the FMA pipe (magic-number exp2, deg-5 poly; |rel err| ~1e-7)
__device__ __forceinline__ float fast_exp(float x) {
    x = fmaxf(x, -80.f);
    const float LOG2E = 1.4426950408889634f;
    float t = x * LOG2E;
    float r = t + 12582912.f;            // round-to-nearest int via magic
    float i = r - 12582912.f;
    float f = t - i;                     // f in [-0.5, 0.5]
    uint32_t ib = __float_as_uint(r);
    float sc = __uint_as_float((ib + 127u) << 23);   // 2^i
    float p = 1.3333558146e-3f;
    p = fmaf(p, f, 9.6181291076e-3f);
    p = fmaf(p, f, 5.5504108664e-2f);
    p = fmaf(p, f, 2.4022650696e-1f);
    p = fmaf(p, f, 6.9314718056e-1f);
    p = fmaf(p, f, 1.0f);
    return p * sc;
}

// split two floats into packed bf16x2 hi / lo
__device__ __forceinline__ void split2(float a, float b, uint32_t& hp, uint32_t& lp) {
    __nv_bfloat16 ha = __float2bfloat16(a), hb = __float2bfloat16(b);
    __nv_bfloat16 la = __float2bfloat16(a - __bfloat162float(ha));
    __nv_bfloat16 lb = __float2bfloat16(b - __bfloat162float(hb));
    hp = ((uint32_t)__bfloat16_as_ushort(hb) << 16) | __bfloat16_as_ushort(ha);
    lp = ((uint32_t)__bfloat16_as_ushort(lb) << 16) | __bfloat16_as_ushort(la);
}

// ================= split / transpose conversions =================
__global__ void split_x_kernel(const float* __restrict__ x,
                               __nv_bfloat16* __restrict__ hi,
                               __nv_bfloat16* __restrict__ lo)
{
    int i = blockIdx.x * blockDim.x + threadIdx.x;
    float4 v = ((const float4*)x)[i];
    uint32_t h0, l0, h1, l1;
    split2(v.x, v.y, h0, l0);
    split2(v.z, v.w, h1, l1);
    uint2* H = (uint2*)hi;
    uint2* L = (uint2*)lo;
    H[i] = make_uint2(h0, h1);
    L[i] = make_uint2(l0, l1);
}

__global__ void wsplit_t_kernel(const float* __restrict__ W,
                                __nv_bfloat16* __restrict__ th,
                                __nv_bfloat16* __restrict__ tl, int N)
{
    __shared__ float s[32][33];
    const int k0 = blockIdx.y * 32, n0 = blockIdx.x * 32;
    const int tx = threadIdx.x, ty = threadIdx.y;
    s[ty][tx] = W[(size_t)(k0 + ty) * N + n0 + tx];
    __syncthreads();
    float v = s[tx][ty];
    __nv_bfloat16 h = __float2bfloat16(v);
    __nv_bfloat16 l = __float2bfloat16(v - __bfloat162float(h));
    size_t o = (size_t)(n0 + ty) * D_ + k0 + tx;
    th[o] = h;
    tl[o] = l;
}

// ================= split-bf16 GEMM via mma.sync (validated R4) =================
#define GK        2048
#define NCH       (GK/64)
#define TILEB     16384
#define STAGEB    (4*TILEB)
#define GEMM_SMEM (2*STAGEB + 1024)

__global__ void __launch_bounds__(256, 1) gemm_mma_kernel(
    const __nv_bfloat16* __restrict__ ah, const __nv_bfloat16* __restrict__ al,
    const __nv_bfloat16* __restrict__ wth, const __nv_bfloat16* __restrict__ wtl,
    float* __restrict__ C, int N)
{
    extern __shared__ char sm[];
    const uint32_t smb   = smem_u32(sm);
    const uint32_t tiles = (smb + 1023u) & ~1023u;

    const int tid  = threadIdx.x;
    const int wid  = tid >> 5, lane = tid & 31;
    const int wm   = wid & 3,  wn   = wid >> 2;
    const int m0   = blockIdx.y << 7;
    const int n0   = blockIdx.x << 7;

    const __nv_bfloat16* srcs[4] = { ah  + (size_t)m0 * GK, al  + (size_t)m0 * GK,
                                     wth + (size_t)n0 * GK, wtl + (size_t)n0 * GK };

    float acc[2][8][4];
#pragma unroll
    for (int i = 0; i < 2; i++)
#pragma unroll
        for (int j = 0; j < 8; j++)
#pragma unroll
            for (int q = 0; q < 4; q++) acc[i][j][q] = 0.f;

    auto prefetch = [&](int ch) {
        const uint32_t stage = tiles + (uint32_t)(ch & 1) * STAGEB;
        const int ke = ch << 6;
#pragma unroll
        for (int t = 0; t < 4; t++) {
            const __nv_bfloat16* s = srcs[t];
#pragma unroll
            for (int j = 0; j < 4; j++) {
                int idx = tid + (j << 8);
                int r   = idx >> 3;
                int c   = idx & 7;
                cp_async16(stage + t * TILEB + sw128((r << 7) + (c << 4)),
                           s + (size_t)r * GK + ke + (c << 3));
            }
        }
        CP_COMMIT();
    };

    prefetch(0);

    for (int ch = 0; ch < NCH; ch++) {
        if (ch + 1 < NCH) { prefetch(ch + 1); CP_WAIT(1); }
        else              { CP_WAIT(0); }
        __syncthreads();

        const uint32_t stage = tiles + (uint32_t)(ch & 1) * STAGEB;
        const uint32_t sAh = stage,            sAl = stage + TILEB;
        const uint32_t sBh = stage + 2*TILEB,  sBl = stage + 3*TILEB;

#pragma unroll
        for (int ks = 0; ks < 4; ks++) {
            const int kb = ks << 5;

            uint32_t ahf[2][4], alf[2][4];
#pragma unroll
            for (int mt = 0; mt < 2; mt++) {
                int row = wm*32 + mt*16 + (lane & 15);
                uint32_t off = sw128((uint32_t)(row << 7) + kb + ((lane >> 4) << 4));
                ldsm_x4(ahf[mt], sAh + off);
                ldsm_x4(alf[mt], sAl + off);
            }
            uint32_t bhf[8][2], blf[8][2];
            const int brow = wn*64 + (lane & 7);
            const int bko  = kb + (((lane >> 3) & 1) << 4);
#pragma unroll
            for (int nt = 0; nt < 8; nt++) {
                uint32_t off = sw128((uint32_t)((brow + nt*8) << 7) + bko);
                ldsm_x2(bhf[nt], sBh + off);
                ldsm_x2(blf[nt], sBl + off);
            }
#pragma unroll
            for (int mt = 0; mt < 2; mt++)
#pragma unroll
                for (int nt = 0; nt < 8; nt++) {
                    mma16816(acc[mt][nt], ahf[mt], bhf[nt]);
                    mma16816(acc[mt][nt], ahf[mt], blf[nt]);
                    mma16816(acc[mt][nt], alf[mt], bhf[nt]);
                }
        }
        __syncthreads();
    }

    const int er = lane >> 2, ec = (lane & 3) << 1;
#pragma unroll
    for (int mt = 0; mt < 2; mt++) {
        int r0 = m0 + wm*32 + mt*16 + er;
#pragma unroll
        for (int nt = 0; nt < 8; nt++) {
            int c = n0 + wn*64 + nt*8 + ec;
            *(float2*)(C + (size_t)r0      * N + c) = make_float2(acc[mt][nt][0], acc[mt][nt][1]);
            *(float2*)(C + (size_t)(r0 + 8)* N + c) = make_float2(acc[mt][nt][2], acc[mt][nt][3]);
        }
    }
}

// ---------------- time-shift mix ----------------
__global__ void mix_kernel(const float* __restrict__ xk, const float* __restrict__ xv,
                           const float* __restrict__ mk, const float* __restrict__ mv,
                           float* __restrict__ ok, float* __restrict__ ov)
{
    const int D4 = D_ / 4;
    int idx = blockIdx.x * blockDim.x + threadIdx.x;
    int d4  = idx & (D4 - 1);
    int tok = idx >> 9;
    int t   = tok & (T_ - 1);

    float4 kc = ((const float4*)xk)[idx];
    float4 vc = ((const float4*)xv)[idx];
    float4 m1 = ((const float4*)mk)[d4];
    float4 m2 = ((const float4*)mv)[d4];
    float4 kp = make_float4(0.f,0.f,0.f,0.f);
    float4 vp = make_float4(0.f,0.f,0.f,0.f);
    if (t > 0) {
        kp = ((const float4*)xk)[idx - D4];
        vp = ((const float4*)xv)[idx - D4];
    }
    float4 r1, r2;
    r1.x = kc.x + m1.x*(kp.x-kc.x);  r1.y = kc.y + m1.y*(kp.y-kc.y);
    r1.z = kc.z + m1.z*(kp.z-kc.z);  r1.w = kc.w + m1.w*(kp.w-kc.w);
    r2.x = vc.x + m2.x*(vp.x-vc.x);  r2.y = vc.y + m2.y*(vp.y-vc.y);
    r2.z = vc.z + m2.z*(vp.z-vc.z);  r2.w = vc.w + m2.w*(vp.w-vc.w);
    ((float4*)ok)[idx] = r1;
    ((float4*)ov)[idx] = r2;
}

// ---------------- per-head RMS norm (+ optional RoPE) ----------------
__global__ void norm_head_kernel(float* __restrict__ x, int heads, int do_rope)
{
    __shared__ float sbuf[4];
    __shared__ float svals[128];
    const int head = blockIdx.x % heads;
    const int tok  = blockIdx.x / heads;
    const int t    = tok % T_;
    float* p = x + (size_t)tok*heads*HD_ + head*HD_;
    const int d = threadIdx.x;

    float v  = p[d];
    float ss = v*v;
#pragma unroll
    for (int o = 16; o > 0; o >>= 1) ss += __shfl_xor_sync(0xffffffffu, ss, o);
    if ((d & 31) == 0) sbuf[d >> 5] = ss;
    __syncthreads();
    float tot = sbuf[0] + sbuf[1] + sbuf[2] + sbuf[3];
    float r   = rsqrtf(tot * (1.f/HD_) + 1e-8f);
    float vn  = v * r;

    if (do_rope) {
        svals[d] = vn;
        __syncthreads();
        int   j  = d & 63;
        float inv_freq = exp2f(-(float)j * (13.287712379549449f / 64.f));
        float ang = (float)t * inv_freq;
        float sn, cs;
        sincosf(ang, &sn, &cs);
        float partner = svals[d ^ 64];
        p[d] = (d < 64) ? (vn*cs - partner*sn) : (vn*cs + partner*sn);
    } else {
        p[d] = vn;
    }
}

// ================= flash attention via mma.sync (split-bf16) =================
// BM=128 q rows, BN=64 kv per tile, HD=128. 8 warps; warp w owns rows 16w..16w+15.
#define FQH 0
#define FQL 32768
#define FKH 65536
#define FKL 81920
#define FVH 98304
#define FVL 114688
#define FLASH_SMEM 131072

__global__ void __launch_bounds__(256, 1) flash_mma_kernel(
    const float* __restrict__ q, const float* __restrict__ k,
    const float* __restrict__ v, float* __restrict__ y)
{
    extern __shared__ char sm[];
    const uint32_t smb = smem_u32(sm);

    const int tid  = threadIdx.x;
    const int w    = tid >> 5, lane = tid & 31;
    const int qt   = blockIdx.x;
    const int b    = blockIdx.y >> 4;
    const int h    = blockIdx.y & 15;
    const int kvh  = h >> 2;
    const int qs   = qt << 7;
    const float scale = 0.08838834764831845f;   // 1/sqrt(128)

    // ---- load Q tile (128x128), scale, split -> smem ----
    {
        const float* qg = q + ((size_t)(b*T_ + qs))*D_ + h*HD_;
#pragma unroll
        for (int it = 0; it < 16; it++) {
            int f  = tid + (it << 8);
            int r  = f >> 5, c4 = f & 31;
            float4 t4 = *(const float4*)(qg + (size_t)r*D_ + (c4 << 2));
            t4.x *= scale; t4.y *= scale; t4.z *= scale; t4.w *= scale;
            uint32_t h0, l0, h1, l1;
            split2(t4.x, t4.y, h0, l0);
            split2(t4.z, t4.w, h1, l1);
            uint32_t off = sw256((r << 8) + (c4 << 3));
            *(uint2*)(sm + FQH + off) = make_uint2(h0, h1);
            *(uint2*)(sm + FQL + off) = make_uint2(l0, l1);
        }
    }

    float o[16][4];
#pragma unroll
    for (int nh = 0; nh < 16; nh++)
#pragma unroll
        for (int qq = 0; qq < 4; qq++) o[nh][qq] = 0.f;
    float m0 = -1e30f, m1 = -1e30f, l0 = 0.f, l1 = 0.f;

    const int nkv = 2*qt + 2;
    for (int kt = 0; kt < nkv; kt++) {
        const int ks = kt << 6;
        __syncthreads();
        // ---- load K,V tiles (64x128), split -> smem ----
        {
            const float* kg = k + ((size_t)(b*T_ + ks))*(KVH_*HD_) + kvh*HD_;
            const float* vg = v + ((size_t)(b*T_ + ks))*(KVH_*HD_) + kvh*HD_;
#pragma unroll
            for (int it = 0; it < 8; it++) {
                int f  = tid + (it << 8);
                int r  = f >> 5, c4 = f & 31;
                uint32_t off = sw256((r << 8) + (c4 << 3));
                float4 t4 = *(const float4*)(kg + (size_t)r*(KVH_*HD_) + (c4 << 2));
                uint32_t h0, lo0, h1, lo1;
                split2(t4.x, t4.y, h0, lo0);
                split2(t4.z, t4.w, h1, lo1);
                *(uint2*)(sm + FKH + off) = make_uint2(h0, h1);
                *(uint2*)(sm + FKL + off) = make_uint2(lo0, lo1);
                float4 u4 = *(const float4*)(vg + (size_t)r*(KVH_*HD_) + (c4 << 2));
                split2(u4.x, u4.y, h0, lo0);
                split2(u4.z, u4.w, h1, lo1);
                *(uint2*)(sm + FVH + off) = make_uint2(h0, h1);
                *(uint2*)(sm + FVL + off) = make_uint2(lo0, lo1);
            }
        }
        __syncthreads();

        // ---- S = Q K^T (3-term split) ----
        float s[8][4];
#pragma unroll
        for (int nt = 0; nt < 8; nt++)
#pragma unroll
            for (int qq = 0; qq < 4; qq++) s[nt][qq] = 0.f;

#pragma unroll
        for (int ks8 = 0; ks8 < 8; ks8++) {
            const int kb = ks8 << 5;
            uint32_t aQh[4], aQl[4];
            {
                int row = (w << 4) + (lane & 15);
                uint32_t off = sw256((uint32_t)(row << 8) + kb + ((lane >> 4) << 4));
                ldsm_x4(aQh, smb + FQH + off);
                ldsm_x4(aQl, smb + FQL + off);
            }
            const int brow = lane & 7;
            const int bko  = kb + (((lane >> 3) & 1) << 4);
#pragma unroll
            for (int nt = 0; nt < 8; nt++) {
                uint32_t off = sw256((uint32_t)((brow + nt*8) << 8) + bko);
                uint32_t bKh[2], bKl[2];
                ldsm_x2(bKh, smb + FKH + off);
                ldsm_x2(bKl, smb + FKL + off);
                mma16816(s[nt], aQh, bKh);
                mma16816(s[nt], aQl, bKh);
                mma16816(s[nt], aQh, bKl);
            }
        }

        // ---- causal mask (only last two kv tiles can cross diagonal) ----
        if (kt >= 2*qt) {
            const int gr0 = qs + (w << 4) + (lane >> 2);
            const int gc0 = ks + ((lane & 3) << 1);
#pragma unroll
            for (int nt = 0; nt < 8; nt++) {
                int c = gc0 + nt*8;
                if (c     > gr0)     s[nt][0] = -1e30f;
                if (c + 1 > gr0)     s[nt][1] = -1e30f;
                if (c     > gr0 + 8) s[nt][2] = -1e30f;
                if (c + 1 > gr0 + 8) s[nt][3] = -1e30f;
            }
        }

        // ---- online softmax (register-local per warp) ----
        float mx0 = -1e30f, mx1 = -1e30f;
#pragma unroll
        for (int nt = 0; nt < 8; nt++) {
            mx0 = fmaxf(mx0, fmaxf(s[nt][0], s[nt][1]));
            mx1 = fmaxf(mx1, fmaxf(s[nt][2], s[nt][3]));
        }
        mx0 = fmaxf(mx0, __shfl_xor_sync(0xffffffffu, mx0, 1));
        mx0 = fmaxf(mx0, __shfl_xor_sync(0xffffffffu, mx0, 2));
        mx1 = fmaxf(mx1, __shfl_xor_sync(0xffffffffu, mx1, 1));
        mx1 = fmaxf(mx1, __shfl_xor_sync(0xffffffffu, mx1, 2));
        float m0n = fmaxf(m0, mx0), m1n = fmaxf(m1, mx1);
        float sc0 = fast_exp(m0 - m0n), sc1 = fast_exp(m1 - m1n);
        m0 = m0n; m1 = m1n;

        float sum0 = 0.f, sum1 = 0.f;
#pragma unroll
        for (int nt = 0; nt < 8; nt++) {
            s[nt][0] = fast_exp(s[nt][0] - m0n); sum0 += s[nt][0];
            s[nt][1] = fast_exp(s[nt][1] - m0n); sum0 += s[nt][1];
            s[nt][2] = fast_exp(s[nt][2] - m1n); sum1 += s[nt][2];
            s[nt][3] = fast_exp(s[nt][3] - m1n); sum1 += s[nt][3];
        }
        sum0 += __shfl_xor_sync(0xffffffffu, sum0, 1);
        sum0 += __shfl_xor_sync(0xffffffffu, sum0, 2);
        sum1 += __shfl_xor_sync(0xffffffffu, sum1, 1);
        sum1 += __shfl_xor_sync(0xffffffffu, sum1, 2);
        l0 = l0*sc0 + sum0;
        l1 = l1*sc1 + sum1;

#pragma unroll
        for (int nh = 0; nh < 16; nh++) {
            o[nh][0] *= sc0; o[nh][1] *= sc0;
            o[nh][2] *= sc1; o[nh][3] *= sc1;
        }

        // ---- O += P V (3-term split; P a-frags repacked from S c-frags) ----
#pragma unroll
        for (int j = 0; j < 4; j++) {
            uint32_t aPh[4], aPl[4];
            split2(s[2*j][0],   s[2*j][1],   aPh[0], aPl[0]);
            split2(s[2*j][2],   s[2*j][3],   aPh[1], aPl[1]);
            split2(s[2*j+1][0], s[2*j+1][1], aPh[2], aPl[2]);
            split2(s[2*j+1][2], s[2*j+1][3], aPh[3], aPl[3]);
            const uint32_t vrow = (j << 4) + (lane & 15);
#pragma unroll
            for (int nh = 0; nh < 16; nh++) {
                uint32_t off = sw256((vrow << 8) + (nh << 4));
                uint32_t bVh[2], bVl[2];
                ldsm_x2_t(bVh, smb + FVH + off);
                ldsm_x2_t(bVl, smb + FVL + off);
                mma16816(o[nh], aPh, bVh);
                mma16816(o[nh], aPl, bVh);
                mma16816(o[nh], aPh, bVl);
            }
        }
    }

    // ---- finalize: divide by l, write y ----
    const float inv0 = 1.f / l0, inv1 = 1.f / l1;
    const int r0 = qs + (w << 4) + (lane >> 2);
    float* yg0 = y + ((size_t)(b*T_) + r0)*D_ + h*HD_ + ((lane & 3) << 1);
    float* yg1 = yg0 + (size_t)8*D_;
#pragma unroll
    for (int nh = 0; nh < 16; nh++) {
        *(float2*)(yg0 + nh*8) = make_float2(o[nh][0]*inv0, o[nh][1]*inv0);
        *(float2*)(yg1 + nh*8) = make_float2(o[nh][2]*inv1, o[nh][3]*inv1);
    }
}

// ---------------- L2 norm per head + gate ----------------
__global__ void gate_l2_kernel(float* __restrict__ y, const float* __restrict__ g)
{
    __shared__ float sbuf[4];
    const int head = blockIdx.x % H_;
    const int tok  = blockIdx.x / H_;
    float*       yp = y + (size_t)tok*D_ + head*HD_;
    const float* gp = g + (size_t)tok*D_ + head*HD_;
    const int d = threadIdx.x;

    float v  = yp[d];
    float ss = v*v;
#pragma unroll
    for (int o = 16; o > 0; o >>= 1) ss += __shfl_xor_sync(0xffffffffu, ss, o);
    if ((d & 31) == 0) sbuf[d >> 5] = ss;
    __syncthreads();
    float tot = sbuf[0] + sbuf[1] + sbuf[2] + sbuf[3];
    float n   = sqrtf(tot);
    yp[d] = gp[d] * v / fmaxf(n, 1e-12f);
}

// ---------------- final RMS norm over D, scaled by 1/sqrt(48) ----------------
__global__ void final_norm_kernel(const float* __restrict__ in, float* __restrict__ out)
{
    __shared__ float sbuf[8];
    const int tok = blockIdx.x;
    const float* p = in + (size_t)tok*D_;
    const int base = threadIdx.x * 8;

    float4 a = *(const float4*)(p + base);
    float4 b = *(const float4*)(p + base + 4);
    float ss = a.x*a.x + a.y*a.y + a.z*a.z + a.w*a.w
             + b.x*b.x + b.y*b.y + b.z*b.z + b.w*b.w;
#pragma unroll
    for (int o = 16; o > 0; o >>= 1) ss += __shfl_xor_sync(0xffffffffu, ss, o);
    if ((threadIdx.x & 31) == 0) sbuf[threadIdx.x >> 5] = ss;
    __syncthreads();
    float tot = 0.f;
#pragma unroll
    for (int i = 0; i < 8; i++) tot += sbuf[i];
    float r = rsqrtf(tot * (1.f/D_) + 1e-8f) * 0.14433756729740643f;

    float* q = out + (size_t)tok*D_;
    a.x*=r; a.y*=r; a.z*=r; a.w*=r;
    b.x*=r; b.y*=r; b.z*=r; b.w*=r;
    *(float4*)(q + base)     = a;
    *(float4*)(q + base + 4) = b;
}

// ---------------- launcher ----------------
extern "C" void kernel_launch(void* const* d_in, const int* in_sizes, int n_in,
                              void* d_out, int out_size)
{
    (void)in_sizes; (void)n_in; (void)out_size;
    const float* xq = (const float*)d_in[0];
    const float* xk = (const float*)d_in[1];
    const float* xv = (const float*)d_in[2];
    const float* Wq = (const float*)d_in[3];
    const float* Wk = (const float*)d_in[4];
    const float* Wv = (const float*)d_in[5];
    const float* Wg = (const float*)d_in[6];
    const float* Wo = (const float*)d_in[7];
    const float* mk = (const float*)d_in[8];
    const float* mv = (const float*)d_in[9];
    float* out = (float*)d_out;

    float *pxkm, *pxvm, *pq, *pk, *pv, *pg, *py, *po;
    __nv_bfloat16 *pah, *pal, *pwth, *pwtl;
    cudaGetSymbolAddress((void**)&pxkm, g_xkm);
    cudaGetSymbolAddress((void**)&pxvm, g_xvm);
    cudaGetSymbolAddress((void**)&pq,   g_q);
    cudaGetSymbolAddress((void**)&pk,   g_k);
    cudaGetSymbolAddress((void**)&pv,   g_v);
    cudaGetSymbolAddress((void**)&pg,   g_g);
    cudaGetSymbolAddress((void**)&py,   g_y);
    cudaGetSymbolAddress((void**)&po,   g_o);
    cudaGetSymbolAddress((void**)&pah,  g_ah);
    cudaGetSymbolAddress((void**)&pal,  g_al);
    cudaGetSymbolAddress((void**)&pwth, g_wth);
    cudaGetSymbolAddress((void**)&pwtl, g_wtl);

    cudaFuncSetAttribute(gemm_mma_kernel, cudaFuncAttributeMaxDynamicSharedMemorySize,
                         GEMM_SMEM);
    cudaFuncSetAttribute(flash_mma_kernel, cudaFuncAttributeMaxDynamicSharedMemorySize,
                         FLASH_SMEM);

    const int XS_GRID = (NTOK*D_/4)/256;
    dim3 wgrid_full(D_/32, D_/32), wgrid_kv(512/32, D_/32), wblk(32, 32);

    // 1) time-shift mix for k/v paths
    mix_kernel<<<XS_GRID, 256>>>(xk, xv, mk, mv, pxkm, pxvm);

    // 2) q-side projections (xq -> Wq, Wg)
    split_x_kernel<<<XS_GRID, 256>>>(xq, pah, pal);
    wsplit_t_kernel<<<wgrid_full, wblk>>>(Wq, pwth, pwtl, D_);
    gemm_mma_kernel<<<dim3(D_/128, NTOK/128), 256, GEMM_SMEM>>>(pah, pal, pwth, pwtl, pq, D_);
    wsplit_t_kernel<<<wgrid_full, wblk>>>(Wg, pwth, pwtl, D_);
    gemm_mma_kernel<<<dim3(D_/128, NTOK/128), 256, GEMM_SMEM>>>(pah, pal, pwth, pwtl, pg, D_);

    // 3) k/v projections
    split_x_kernel<<<XS_GRID, 256>>>(pxkm, pah, pal);
    wsplit_t_kernel<<<wgrid_kv, wblk>>>(Wk, pwth, pwtl, 512);
    gemm_mma_kernel<<<dim3(512/128, NTOK/128), 256, GEMM_SMEM>>>(pah, pal, pwth, pwtl, pk, 512);
    split_x_kernel<<<XS_GRID, 256>>>(pxvm, pah, pal);
    wsplit_t_kernel<<<wgrid_kv, wblk>>>(Wv, pwth, pwtl, 512);
    gemm_mma_kernel<<<dim3(512/128, NTOK/128), 256, GEMM_SMEM>>>(pah, pal, pwth, pwtl, pv, 512);

    // 4) per-head RMS norm (+RoPE for q,k)
    norm_head_kernel<<<NTOK*H_,   128>>>(pq, H_,   1);
    norm_head_kernel<<<NTOK*KVH_, 128>>>(pk, KVH_, 1);
    norm_head_kernel<<<NTOK*KVH_, 128>>>(pv, KVH_, 0);

    // 5) causal GQA attention (tensor-core flash)
    flash_mma_kernel<<<dim3(T_/128, B_*H_), 256, FLASH_SMEM>>>(pq, pk, pv, py);

    // 6) per-head L2 norm + gate
    gate_l2_kernel<<<NTOK*H_, 128>>>(py, pg);

    // 7) output projection
    split_x_kernel<<<XS_GRID, 256>>>(py, pah, pal);
    wsplit_t_kernel<<<wgrid_full, wblk>>>(Wo, pwth, pwtl, D_);
    gemm_mma_kernel<<<dim3(D_/128, NTOK/128), 256, GEMM_SMEM>>>(pah, pal, pwth, pwtl, po, D_);

    // 8) final RMS norm + 1/sqrt(2*N_LAYER)
    final_norm_kernel<<<NTOK, 256>>>(po, out);
}

// round 7
// speedup vs baseline: 3.1222x; 1.1391x over previous
#include <cuda_runtime.h>
#include <cuda_bf16.h>
#include <math.h>
#include <stdint.h>

#define B_    2
#define T_    2048
#define D_    2048
#define H_    16
#define KVH_  4
#define HD_   128
#define NTOK  (B_*T_)

// ---------------- scratch (device globals: allocation-free) ----------------
__device__ float g_xkm[NTOK*D_];
__device__ float g_xvm[NTOK*D_];
__device__ float g_q  [NTOK*D_];
__device__ float g_k  [NTOK*KVH_*HD_];
__device__ float g_v  [NTOK*KVH_*HD_];
__device__ float g_g  [NTOK*D_];
__device__ float g_y  [NTOK*D_];
__device__ float g_o  [NTOK*D_];
// split-bf16 operands
__device__ __align__(16) __nv_bfloat16 g_ah [NTOK*D_];
__device__ __align__(16) __nv_bfloat16 g_al [NTOK*D_];
__device__ __align__(16) __nv_bfloat16 g_wth[2*D_*D_];
__device__ __align__(16) __nv_bfloat16 g_wtl[2*D_*D_];
// pre-split attention operands
__device__ __align__(16) __nv_bfloat16 g_qh [NTOK*D_];
__device__ __align__(16) __nv_bfloat16 g_ql [NTOK*D_];
__device__ __align__(16) __nv_bfloat16 g_kh [NTOK*KVH_*HD_];
__device__ __align__(16) __nv_bfloat16 g_kl [NTOK*KVH_*HD_];
__device__ __align__(16) __nv_bfloat16 g_vh [NTOK*KVH_*HD_];
__device__ __align__(16) __nv_bfloat16 g_vl [NTOK*KVH_*HD_];

// ================= baseline-ISA helpers =================
__device__ __forceinline__ uint32_t smem_u32(const void* p) {
    uint32_t a;
    asm("{ .reg .u64 t; cvta.to.shared.u64 t, %1; cvt.u32.u64 %0, t; }" : "=r"(a) : "l"(p));
    return a;
}
__device__ __forceinline__ uint32_t sw128(uint32_t off) { return off ^ ((off >> 3) & 0x70); }
__device__ __forceinline__ uint32_t sw256(uint32_t off) { return off ^ ((off >> 4) & 0x70); }

__device__ __forceinline__ void cp_async16(uint32_t dst, const void* src) {
    asm volatile("cp.async.cg.shared.global [%0], [%1], 16;" :: "r"(dst), "l"(src) : "memory");
}
#define CP_COMMIT() asm volatile("cp.async.commit_group;" ::: "memory")
#define CP_WAIT(n)  asm volatile("cp.async.wait_group %0;" :: "n"(n) : "memory")

__device__ __forceinline__ void ldsm_x4(uint32_t* r, uint32_t addr) {
    asm volatile("ldmatrix.sync.aligned.m8n8.x4.shared.b16 {%0,%1,%2,%3}, [%4];"
                 : "=r"(r[0]), "=r"(r[1]), "=r"(r[2]), "=r"(r[3]) : "r"(addr));
}
__device__ __forceinline__ void ldsm_x4_t(uint32_t* r, uint32_t addr) {
    asm volatile("ldmatrix.sync.aligned.m8n8.x4.trans.shared.b16 {%0,%1,%2,%3}, [%4];"
                 : "=r"(r[0]), "=r"(r[1]), "=r"(r[2]), "=r"(r[3]) : "r"(addr));
}
__device__ __forceinline__ void mma16816(float* d, const uint32_t* a, const uint32_t* b) {
    asm volatile("mma.sync.aligned.m16n8k16.row.col.f32.bf16.bf16.f32 "
                 "{%0,%1,%2,%3}, {%4,%5,%6,%7}, {%8,%9}, {%0,%1,%2,%3};"
                 : "+f"(d[0]), "+f"(d[1]), "+f"(d[2]), "+f"(d[3])
                 : "r"(a[0]), "r"(a[1]), "r"(a[2]), "r"(a[3]), "r"(b[0]), "r"(b[1]));
}

// fast exp on the FMA pipe (magic-number exp2, deg-5 poly; |rel err| ~1e-7)
__device__ __forceinline__ float fast_exp(float x) {
    x = fmaxf(x, -80.f);
    const float LOG2E = 1.4426950408889634f;
    float t = x * LOG2E;
    float r = t + 12582912.f;
    float i = r - 12582912.f;
    float f = t - i;
    uint32_t ib = __float_as_uint(r);
    float sc = __uint_as_float((ib + 127u) << 23);
    float p = 1.3333558146e-3f;
    p = fmaf(p, f, 9.6181291076e-3f);
    p = fmaf(p, f, 5.5504108664e-2f);
    p = fmaf(p, f, 2.4022650696e-1f);
    p = fmaf(p, f, 6.9314718056e-1f);
    p = fmaf(p, f, 1.0f);
    return p * sc;
}

// split two floats into packed bf16x2 hi / lo
__device__ __forceinline__ void split2(float a, float b, uint32_t& hp, uint32_t& lp) {
    __nv_bfloat16 ha = __float2bfloat16(a), hb = __float2bfloat16(b);
    __nv_bfloat16 la = __float2bfloat16(a - __bfloat162float(ha));
    __nv_bfloat16 lb = __float2bfloat16(b - __bfloat162float(hb));
    hp = ((uint32_t)__bfloat16_as_ushort(hb) << 16) | __bfloat16_as_ushort(ha);
    lp = ((uint32_t)__bfloat16_as_ushort(lb) << 16) | __bfloat16_as_ushort(la);
}

// ================= split / transpose conversions =================
__global__ void split_x_kernel(const float* __restrict__ x,
                               __nv_bfloat16* __restrict__ hi,
                               __nv_bfloat16* __restrict__ lo)
{
    int i = blockIdx.x * blockDim.x + threadIdx.x;
    float4 v = ((const float4*)x)[i];
    uint32_t h0, l0, h1, l1;
    split2(v.x, v.y, h0, l0);
    split2(v.z, v.w, h1, l1);
    uint2* H = (uint2*)hi;
    uint2* L = (uint2*)lo;
    H[i] = make_uint2(h0, h1);
    L[i] = make_uint2(l0, l1);
}

__global__ void wsplit_t_kernel(const float* __restrict__ W,
                                __nv_bfloat16* __restrict__ th,
                                __nv_bfloat16* __restrict__ tl, int N)
{
    __shared__ float s[32][33];
    const int k0 = blockIdx.y * 32, n0 = blockIdx.x * 32;
    const int tx = threadIdx.x, ty = threadIdx.y;
    s[ty][tx] = W[(size_t)(k0 + ty) * N + n0 + tx];
    __syncthreads();
    float v = s[tx][ty];
    __nv_bfloat16 h = __float2bfloat16(v);
    __nv_bfloat16 l = __float2bfloat16(v - __bfloat162float(h));
    size_t o = (size_t)(n0 + ty) * D_ + k0 + tx;
    th[o] = h;
    tl[o] = l;
}

// ================= split-bf16 GEMM via mma.sync =================
// C[M,Ntot] = A[M,2048] @ W[2048,Ntot]; 3-stage cp.async; x4 B loads.
// Output split: columns < cstride go to C0, else C1 (col - cstride).
#define GK        2048
#define NCH       (GK/64)
#define TILEB     16384
#define STAGEB    (4*TILEB)
#define GEMM_SMEM (3*STAGEB + 1024)

__global__ void __launch_bounds__(256, 1) gemm_mma_kernel(
    const __nv_bfloat16* __restrict__ ah, const __nv_bfloat16* __restrict__ al,
    const __nv_bfloat16* __restrict__ wth, const __nv_bfloat16* __restrict__ wtl,
    float* __restrict__ C0, float* __restrict__ C1, int cstride)
{
    extern __shared__ char sm[];
    const uint32_t smb   = smem_u32(sm);
    const uint32_t tiles = (smb + 1023u) & ~1023u;

    const int tid  = threadIdx.x;
    const int wid  = tid >> 5, lane = tid & 31;
    const int wm   = wid & 3,  wn   = wid >> 2;
    const int m0   = blockIdx.y << 7;
    const int n0   = blockIdx.x << 7;

    const __nv_bfloat16* srcs[4] = { ah  + (size_t)m0 * GK, al  + (size_t)m0 * GK,
                                     wth + (size_t)n0 * GK, wtl + (size_t)n0 * GK };

    float acc[2][8][4];
#pragma unroll
    for (int i = 0; i < 2; i++)
#pragma unroll
        for (int j = 0; j < 8; j++)
#pragma unroll
            for (int q = 0; q < 4; q++) acc[i][j][q] = 0.f;

    auto prefetch = [&](int ch) {
        const uint32_t stage = tiles + (uint32_t)(ch % 3) * STAGEB;
        const int ke = ch << 6;
#pragma unroll
        for (int t = 0; t < 4; t++) {
            const __nv_bfloat16* s = srcs[t];
#pragma unroll
            for (int j = 0; j < 4; j++) {
                int idx = tid + (j << 8);
                int r   = idx >> 3;
                int c   = idx & 7;
                cp_async16(stage + t * TILEB + sw128((r << 7) + (c << 4)),
                           s + (size_t)r * GK + ke + (c << 3));
            }
        }
        CP_COMMIT();
    };

    prefetch(0);
    prefetch(1);

    for (int ch = 0; ch < NCH; ch++) {
        if (ch + 2 < NCH)      { prefetch(ch + 2); CP_WAIT(2); }
        else if (ch + 1 < NCH) { CP_WAIT(1); }
        else                   { CP_WAIT(0); }
        __syncthreads();

        const uint32_t stage = tiles + (uint32_t)(ch % 3) * STAGEB;
        const uint32_t sAh = stage,            sAl = stage + TILEB;
        const uint32_t sBh = stage + 2*TILEB,  sBl = stage + 3*TILEB;

#pragma unroll
        for (int ks = 0; ks < 4; ks++) {
            const int kb = ks << 5;

            uint32_t ahf[2][4], alf[2][4];
#pragma unroll
            for (int mt = 0; mt < 2; mt++) {
                int row = wm*32 + mt*16 + (lane & 15);
                uint32_t off = sw128((uint32_t)(row << 7) + kb + ((lane >> 4) << 4));
                ldsm_x4(ahf[mt], sAh + off);
                ldsm_x4(alf[mt], sAl + off);
            }
            const int brow4 = wn*64 + (lane & 7) + ((lane >> 4) << 3);
            const int bko   = kb + (((lane >> 3) & 1) << 4);
#pragma unroll
            for (int np = 0; np < 4; np++) {
                uint32_t bh[4], bl[4];
                uint32_t off = sw128((uint32_t)((brow4 + np*16) << 7) + bko);
                ldsm_x4(bh, sBh + off);
                ldsm_x4(bl, sBl + off);
#pragma unroll
                for (int mt = 0; mt < 2; mt++) {
                    mma16816(acc[mt][2*np],   ahf[mt], bh);
                    mma16816(acc[mt][2*np],   ahf[mt], bl);
                    mma16816(acc[mt][2*np],   alf[mt], bh);
                    mma16816(acc[mt][2*np+1], ahf[mt], bh + 2);
                    mma16816(acc[mt][2*np+1], ahf[mt], bl + 2);
                    mma16816(acc[mt][2*np+1], alf[mt], bh + 2);
                }
            }
        }
        __syncthreads();
    }

    float* C = C0;
    int nc = n0;
    if (C1 != nullptr && n0 >= cstride) { C = C1; nc = n0 - cstride; }

    const int er = lane >> 2, ec = (lane & 3) << 1;
#pragma unroll
    for (int mt = 0; mt < 2; mt++) {
        int r0 = m0 + wm*32 + mt*16 + er;
#pragma unroll
        for (int nt = 0; nt < 8; nt++) {
            int c = nc + wn*64 + nt*8 + ec;
            *(float2*)(C + (size_t)r0      * cstride + c) = make_float2(acc[mt][nt][0], acc[mt][nt][1]);
            *(float2*)(C + (size_t)(r0 + 8)* cstride + c) = make_float2(acc[mt][nt][2], acc[mt][nt][3]);
        }
    }
}

// ---------------- time-shift mix ----------------
__global__ void mix_kernel(const float* __restrict__ xk, const float* __restrict__ xv,
                           const float* __restrict__ mk, const float* __restrict__ mv,
                           float* __restrict__ ok, float* __restrict__ ov)
{
    const int D4 = D_ / 4;
    int idx = blockIdx.x * blockDim.x + threadIdx.x;
    int d4  = idx & (D4 - 1);
    int tok = idx >> 9;
    int t   = tok & (T_ - 1);

    float4 kc = ((const float4*)xk)[idx];
    float4 vc = ((const float4*)xv)[idx];
    float4 m1 = ((const float4*)mk)[d4];
    float4 m2 = ((const float4*)mv)[d4];
    float4 kp = make_float4(0.f,0.f,0.f,0.f);
    float4 vp = make_float4(0.f,0.f,0.f,0.f);
    if (t > 0) {
        kp = ((const float4*)xk)[idx - D4];
        vp = ((const float4*)xv)[idx - D4];
    }
    float4 r1, r2;
    r1.x = kc.x + m1.x*(kp.x-kc.x);  r1.y = kc.y + m1.y*(kp.y-kc.y);
    r1.z = kc.z + m1.z*(kp.z-kc.z);  r1.w = kc.w + m1.w*(kp.w-kc.w);
    r2.x = vc.x + m2.x*(vp.x-vc.x);  r2.y = vc.y + m2.y*(vp.y-vc.y);
    r2.z = vc.z + m2.z*(vp.z-vc.z);  r2.w = vc.w + m2.w*(vp.w-vc.w);
    ((float4*)ok)[idx] = r1;
    ((float4*)ov)[idx] = r2;
}

// ------- per-head RMS norm (+ optional RoPE), emits bf16 hi/lo split -------
__global__ void norm_head_split_kernel(const float* __restrict__ x, int heads,
                                       int do_rope, float scale,
                                       __nv_bfloat16* __restrict__ oh,
                                       __nv_bfloat16* __restrict__ ol)
{
    __shared__ float sbuf[4];
    __shared__ float svals[128];
    const int head = blockIdx.x % heads;
    const int tok  = blockIdx.x / heads;
    const int t    = tok % T_;
    const size_t base = (size_t)tok*heads*HD_ + head*HD_;
    const float* p = x + base;
    const int d = threadIdx.x;

    float v  = p[d];
    float ss = v*v;
#pragma unroll
    for (int o = 16; o > 0; o >>= 1) ss += __shfl_xor_sync(0xffffffffu, ss, o);
    if ((d & 31) == 0) sbuf[d >> 5] = ss;
    __syncthreads();
    float tot = sbuf[0] + sbuf[1] + sbuf[2] + sbuf[3];
    float r   = rsqrtf(tot * (1.f/HD_) + 1e-8f);
    float vn  = v * r;
    float f;

    if (do_rope) {
        svals[d] = vn;
        __syncthreads();
        int   j  = d & 63;
        float inv_freq = exp2f(-(float)j * (13.287712379549449f / 64.f));
        float ang = (float)t * inv_freq;
        float sn, cs;
        sincosf(ang, &sn, &cs);
        float partner = svals[d ^ 64];
        f = (d < 64) ? (vn*cs - partner*sn) : (vn*cs + partner*sn);
    } else {
        f = vn;
    }
    f *= scale;
    __nv_bfloat16 h = __float2bfloat16(f);
    __nv_bfloat16 l = __float2bfloat16(f - __bfloat162float(h));
    oh[base + d] = h;
    ol[base + d] = l;
}

// ================= flash attention via mma.sync (pre-split operands) =======
// BM=128 q rows, BN=64 kv per tile, HD=128. 8 warps; warp w owns rows 16w..16w+15.
#define FQH  0
#define FQL  32768
#define FKV  65536
#define FSTG 65536      /* per stage: KH,KL,VH,VL x 16KB */
#define FLASH_SMEM (FKV + 2*FSTG)

__global__ void __launch_bounds__(256, 1) flash_mma_kernel(
    const __nv_bfloat16* __restrict__ qh, const __nv_bfloat16* __restrict__ ql,
    const __nv_bfloat16* __restrict__ kh, const __nv_bfloat16* __restrict__ kl,
    const __nv_bfloat16* __restrict__ vh, const __nv_bfloat16* __restrict__ vl,
    float* __restrict__ y)
{
    extern __shared__ char sm[];
    const uint32_t smb = smem_u32(sm);

    const int tid  = threadIdx.x;
    const int w    = tid >> 5, lane = tid & 31;
    const int qt   = blockIdx.x;
    const int b    = blockIdx.y >> 4;
    const int h    = blockIdx.y & 15;
    const int kvh  = h >> 2;
    const int qs   = qt << 7;

    // ---- async load Q tile (128x128 bf16 hi+lo) ----
    {
        const __nv_bfloat16* qgh = qh + ((size_t)(b*T_ + qs))*D_ + h*HD_;
        const __nv_bfloat16* qgl = ql + ((size_t)(b*T_ + qs))*D_ + h*HD_;
#pragma unroll
        for (int it = 0; it < 8; it++) {
            int idx = tid + (it << 8);
            int r = idx >> 4, c = idx & 15;
            uint32_t off = sw256((r << 8) + (c << 4));
            cp_async16(smb + FQH + off, qgh + (size_t)r*D_ + (c << 3));
            cp_async16(smb + FQL + off, qgl + (size_t)r*D_ + (c << 3));
        }
        CP_COMMIT();
    }

    const __nv_bfloat16* kh_b = kh + (size_t)(b*T_)*(KVH_*HD_) + kvh*HD_;
    const __nv_bfloat16* kl_b = kl + (size_t)(b*T_)*(KVH_*HD_) + kvh*HD_;
    const __nv_bfloat16* vh_b = vh + (size_t)(b*T_)*(KVH_*HD_) + kvh*HD_;
    const __nv_bfloat16* vl_b = vl + (size_t)(b*T_)*(KVH_*HD_) + kvh*HD_;

    auto prefetch_kv = [&](int kt) {
        const uint32_t sb = smb + FKV + (uint32_t)(kt & 1)*FSTG;
        const size_t rb = (size_t)(kt << 6) * (KVH_*HD_);
        const __nv_bfloat16* ps[4] = { kh_b + rb, kl_b + rb, vh_b + rb, vl_b + rb };
#pragma unroll
        for (int t = 0; t < 4; t++) {
#pragma unroll
            for (int it = 0; it < 4; it++) {
                int idx = tid + (it << 8);
                int r = idx >> 4, c = idx & 15;
                cp_async16(sb + t*16384 + sw256((r << 8) + (c << 4)),
                           ps[t] + (size_t)r*(KVH_*HD_) + (c << 3));
            }
        }
        CP_COMMIT();
    };

    prefetch_kv(0);

    float o[16][4];
#pragma unroll
    for (int nh = 0; nh < 16; nh++)
#pragma unroll
        for (int qq = 0; qq < 4; qq++) o[nh][qq] = 0.f;
    float m0 = -1e30f, m1 = -1e30f, l0 = 0.f, l1 = 0.f;

    const int nkv = 2*qt + 2;
    for (int kt = 0; kt < nkv; kt++) {
        const int ks = kt << 6;
        if (kt + 1 < nkv) { prefetch_kv(kt + 1); CP_WAIT(1); }
        else              { CP_WAIT(0); }
        __syncthreads();

        const uint32_t sb  = smb + FKV + (uint32_t)(kt & 1)*FSTG;
        const uint32_t sKH = sb, sKL = sb + 16384, sVH = sb + 32768, sVL = sb + 49152;

        // ---- S = Q K^T (3-term split) ----
        float s[8][4];
#pragma unroll
        for (int nt = 0; nt < 8; nt++)
#pragma unroll
            for (int qq = 0; qq < 4; qq++) s[nt][qq] = 0.f;

#pragma unroll
        for (int ks8 = 0; ks8 < 8; ks8++) {
            const int kb = ks8 << 5;
            uint32_t aQh[4], aQl[4];
            {
                int row = (w << 4) + (lane & 15);
                uint32_t off = sw256((uint32_t)(row << 8) + kb + ((lane >> 4) << 4));
                ldsm_x4(aQh, smb + FQH + off);
                ldsm_x4(aQl, smb + FQL + off);
            }
            const int brow4 = (lane & 7) + ((lane >> 4) << 3);
            const int bko   = kb + (((lane >> 3) & 1) << 4);
#pragma unroll
            for (int np = 0; np < 4; np++) {
                uint32_t bh[4], bl[4];
                uint32_t off = sw256((uint32_t)((brow4 + np*16) << 8) + bko);
                ldsm_x4(bh, sKH + off);
                ldsm_x4(bl, sKL + off);
                mma16816(s[2*np],   aQh, bh);
                mma16816(s[2*np],   aQl, bh);
                mma16816(s[2*np],   aQh, bl);
                mma16816(s[2*np+1], aQh, bh + 2);
                mma16816(s[2*np+1], aQl, bh + 2);
                mma16816(s[2*np+1], aQh, bl + 2);
            }
        }

        // ---- causal mask ----
        if (kt >= 2*qt) {
            const int gr0 = qs + (w << 4) + (lane >> 2);
            const int gc0 = ks + ((lane & 3) << 1);
#pragma unroll
            for (int nt = 0; nt < 8; nt++) {
                int c = gc0 + nt*8;
                if (c     > gr0)     s[nt][0] = -1e30f;
                if (c + 1 > gr0)     s[nt][1] = -1e30f;
                if (c     > gr0 + 8) s[nt][2] = -1e30f;
                if (c + 1 > gr0 + 8) s[nt][3] = -1e30f;
            }
        }

        // ---- online softmax (register-local per warp) ----
        float mx0 = -1e30f, mx1 = -1e30f;
#pragma unroll
        for (int nt = 0; nt < 8; nt++) {
            mx0 = fmaxf(mx0, fmaxf(s[nt][0], s[nt][1]));
            mx1 = fmaxf(mx1, fmaxf(s[nt][2], s[nt][3]));
        }
        mx0 = fmaxf(mx0, __shfl_xor_sync(0xffffffffu, mx0, 1));
        mx0 = fmaxf(mx0, __shfl_xor_sync(0xffffffffu, mx0, 2));
        mx1 = fmaxf(mx1, __shfl_xor_sync(0xffffffffu, mx1, 1));
        mx1 = fmaxf(mx1, __shfl_xor_sync(0xffffffffu, mx1, 2));
        float m0n = fmaxf(m0, mx0), m1n = fmaxf(m1, mx1);
        float sc0 = fast_exp(m0 - m0n), sc1 = fast_exp(m1 - m1n);
        m0 = m0n; m1 = m1n;

        float sum0 = 0.f, sum1 = 0.f;
#pragma unroll
        for (int nt = 0; nt < 8; nt++) {
            s[nt][0] = fast_exp(s[nt][0] - m0n); sum0 += s[nt][0];
            s[nt][1] = fast_exp(s[nt][1] - m0n); sum0 += s[nt][1];
            s[nt][2] = fast_exp(s[nt][2] - m1n); sum1 += s[nt][2];
            s[nt][3] = fast_exp(s[nt][3] - m1n); sum1 += s[nt][3];
        }
        sum0 += __shfl_xor_sync(0xffffffffu, sum0, 1);
        sum0 += __shfl_xor_sync(0xffffffffu, sum0, 2);
        sum1 += __shfl_xor_sync(0xffffffffu, sum1, 1);
        sum1 += __shfl_xor_sync(0xffffffffu, sum1, 2);
        l0 = l0*sc0 + sum0;
        l1 = l1*sc1 + sum1;

#pragma unroll
        for (int nh = 0; nh < 16; nh++) {
            o[nh][0] *= sc0; o[nh][1] *= sc0;
            o[nh][2] *= sc1; o[nh][3] *= sc1;
        }

        // ---- O += P V (3-term split; P a-frags repacked from S c-frags) ----
#pragma unroll
        for (int j = 0; j < 4; j++) {
            uint32_t aPh[4], aPl[4];
            split2(s[2*j][0],   s[2*j][1],   aPh[0], aPl[0]);
            split2(s[2*j][2],   s[2*j][3],   aPh[1], aPl[1]);
            split2(s[2*j+1][0], s[2*j+1][1], aPh[2], aPl[2]);
            split2(s[2*j+1][2], s[2*j+1][3], aPh[3], aPl[3]);
            const uint32_t vrow = (j << 4) + (lane & 15);
            const uint32_t nsel = (lane >> 4);
#pragma unroll
            for (int nhp = 0; nhp < 8; nhp++) {
                uint32_t off = sw256((vrow << 8) + ((2*nhp + nsel) << 4));
                uint32_t bh[4], bl[4];
                ldsm_x4_t(bh, sVH + off);
                ldsm_x4_t(bl, sVL + off);
                mma16816(o[2*nhp],   aPh, bh);
                mma16816(o[2*nhp],   aPl, bh);
                mma16816(o[2*nhp],   aPh, bl);
                mma16816(o[2*nhp+1], aPh, bh + 2);
                mma16816(o[2*nhp+1], aPl, bh + 2);
                mma16816(o[2*nhp+1], aPh, bl + 2);
            }
        }
        __syncthreads();
    }

    // ---- finalize: divide by l, write y ----
    const float inv0 = 1.f / l0, inv1 = 1.f / l1;
    const int r0 = qs + (w << 4) + (lane >> 2);
    float* yg0 = y + ((size_t)(b*T_) + r0)*D_ + h*HD_ + ((lane & 3) << 1);
    float* yg1 = yg0 + (size_t)8*D_;
#pragma unroll
    for (int nh = 0; nh < 16; nh++) {
        *(float2*)(yg0 + nh*8) = make_float2(o[nh][0]*inv0, o[nh][1]*inv0);
        *(float2*)(yg1 + nh*8) = make_float2(o[nh][2]*inv1, o[nh][3]*inv1);
    }
}

// ---------------- L2 norm per head + gate ----------------
__global__ void gate_l2_kernel(float* __restrict__ y, const float* __restrict__ g)
{
    __shared__ float sbuf[4];
    const int head = blockIdx.x % H_;
    const int tok  = blockIdx.x / H_;
    float*       yp = y + (size_t)tok*D_ + head*HD_;
    const float* gp = g + (size_t)tok*D_ + head*HD_;
    const int d = threadIdx.x;

    float v  = yp[d];
    float ss = v*v;
#pragma unroll
    for (int o = 16; o > 0; o >>= 1) ss += __shfl_xor_sync(0xffffffffu, ss, o);
    if ((d & 31) == 0) sbuf[d >> 5] = ss;
    __syncthreads();
    float tot = sbuf[0] + sbuf[1] + sbuf[2] + sbuf[3];
    float n   = sqrtf(tot);
    yp[d] = gp[d] * v / fmaxf(n, 1e-12f);
}

// ---------------- final RMS norm over D, scaled by 1/sqrt(48) ----------------
__global__ void final_norm_kernel(const float* __restrict__ in, float* __restrict__ out)
{
    __shared__ float sbuf[8];
    const int tok = blockIdx.x;
    const float* p = in + (size_t)tok*D_;
    const int base = threadIdx.x * 8;

    float4 a = *(const float4*)(p + base);
    float4 b = *(const float4*)(p + base + 4);
    float ss = a.x*a.x + a.y*a.y + a.z*a.z + a.w*a.w
             + b.x*b.x + b.y*b.y + b.z*b.z + b.w*b.w;
#pragma unroll
    for (int o = 16; o > 0; o >>= 1) ss += __shfl_xor_sync(0xffffffffu, ss, o);
    if ((threadIdx.x & 31) == 0) sbuf[threadIdx.x >> 5] = ss;
    __syncthreads();
    float tot = 0.f;
#pragma unroll
    for (int i = 0; i < 8; i++) tot += sbuf[i];
    float r = rsqrtf(tot * (1.f/D_) + 1e-8f) * 0.14433756729740643f;

    float* q = out + (size_t)tok*D_;
    a.x*=r; a.y*=r; a.z*=r; a.w*=r;
    b.x*=r; b.y*=r; b.z*=r; b.w*=r;
    *(float4*)(q + base)     = a;
    *(float4*)(q + base + 4) = b;
}

// ---------------- launcher ----------------
extern "C" void kernel_launch(void* const* d_in, const int* in_sizes, int n_in,
                              void* d_out, int out_size)
{
    (void)in_sizes; (void)n_in; (void)out_size;
    const float* xq = (const float*)d_in[0];
    const float* xk = (const float*)d_in[1];
    const float* xv = (const float*)d_in[2];
    const float* Wq = (const float*)d_in[3];
    const float* Wk = (const float*)d_in[4];
    const float* Wv = (const float*)d_in[5];
    const float* Wg = (const float*)d_in[6];
    const float* Wo = (const float*)d_in[7];
    const float* mk = (const float*)d_in[8];
    const float* mv = (const float*)d_in[9];
    float* out = (float*)d_out;

    float *pxkm, *pxvm, *pq, *pk, *pv, *pg, *py, *po;
    __nv_bfloat16 *pah, *pal, *pwth, *pwtl;
    __nv_bfloat16 *pqh, *pql, *pkh, *pkl, *pvh, *pvl;
    cudaGetSymbolAddress((void**)&pxkm, g_xkm);
    cudaGetSymbolAddress((void**)&pxvm, g_xvm);
    cudaGetSymbolAddress((void**)&pq,   g_q);
    cudaGetSymbolAddress((void**)&pk,   g_k);
    cudaGetSymbolAddress((void**)&pv,   g_v);
    cudaGetSymbolAddress((void**)&pg,   g_g);
    cudaGetSymbolAddress((void**)&py,   g_y);
    cudaGetSymbolAddress((void**)&po,   g_o);
    cudaGetSymbolAddress((void**)&pah,  g_ah);
    cudaGetSymbolAddress((void**)&pal,  g_al);
    cudaGetSymbolAddress((void**)&pwth, g_wth);
    cudaGetSymbolAddress((void**)&pwtl, g_wtl);
    cudaGetSymbolAddress((void**)&pqh,  g_qh);
    cudaGetSymbolAddress((void**)&pql,  g_ql);
    cudaGetSymbolAddress((void**)&pkh,  g_kh);
    cudaGetSymbolAddress((void**)&pkl,  g_kl);
    cudaGetSymbolAddress((void**)&pvh,  g_vh);
    cudaGetSymbolAddress((void**)&pvl,  g_vl);

    cudaFuncSetAttribute(gemm_mma_kernel, cudaFuncAttributeMaxDynamicSharedMemorySize,
                         GEMM_SMEM);
    cudaFuncSetAttribute(flash_mma_kernel, cudaFuncAttributeMaxDynamicSharedMemorySize,
                         FLASH_SMEM);

    const int XS_GRID = (NTOK*D_/4)/256;
    dim3 wgrid_full(D_/32, D_/32), wgrid_kv(512/32, D_/32), wblk(32, 32);

    // 1) time-shift mix for k/v paths
    mix_kernel<<<XS_GRID, 256>>>(xk, xv, mk, mv, pxkm, pxvm);

    // 2) q-side projections: merged N=4096 GEMM (Wq | Wg)
    split_x_kernel<<<XS_GRID, 256>>>(xq, pah, pal);
    wsplit_t_kernel<<<wgrid_full, wblk>>>(Wq, pwth, pwtl, D_);
    wsplit_t_kernel<<<wgrid_full, wblk>>>(Wg, pwth + (size_t)D_*D_, pwtl + (size_t)D_*D_, D_);
    gemm_mma_kernel<<<dim3(4096/128, NTOK/128), 256, GEMM_SMEM>>>(
        pah, pal, pwth, pwtl, pq, pg, D_);

    // 3) k/v projections
    split_x_kernel<<<XS_GRID, 256>>>(pxkm, pah, pal);
    wsplit_t_kernel<<<wgrid_kv, wblk>>>(Wk, pwth, pwtl, 512);
    gemm_mma_kernel<<<dim3(512/128, NTOK/128), 256, GEMM_SMEM>>>(
        pah, pal, pwth, pwtl, pk, nullptr, 512);
    split_x_kernel<<<XS_GRID, 256>>>(pxvm, pah, pal);
    wsplit_t_kernel<<<wgrid_kv, wblk>>>(Wv, pwth, pwtl, 512);
    gemm_mma_kernel<<<dim3(512/128, NTOK/128), 256, GEMM_SMEM>>>(
        pah, pal, pwth, pwtl, pv, nullptr, 512);

    // 4) per-head RMS norm (+RoPE for q,k) with bf16 hi/lo split output
    norm_head_split_kernel<<<NTOK*H_,   128>>>(pq, H_,   1, 0.08838834764831845f, pqh, pql);
    norm_head_split_kernel<<<NTOK*KVH_, 128>>>(pk, KVH_, 1, 1.f, pkh, pkl);
    norm_head_split_kernel<<<NTOK*KVH_, 128>>>(pv, KVH_, 0, 1.f, pvh, pvl);

    // 5) causal GQA attention (tensor-core flash, pre-split operands)
    flash_mma_kernel<<<dim3(T_/128, B_*H_), 256, FLASH_SMEM>>>(
        pqh, pql, pkh, pkl, pvh, pvl, py);

    // 6) per-head L2 norm + gate
    gate_l2_kernel<<<NTOK*H_, 128>>>(py, pg);

    // 7) output projection
    split_x_kernel<<<XS_GRID, 256>>>(py, pah, pal);
    wsplit_t_kernel<<<wgrid_full, wblk>>>(Wo, pwth, pwtl, D_);
    gemm_mma_kernel<<<dim3(D_/128, NTOK/128), 256, GEMM_SMEM>>>(
        pah, pal, pwth, pwtl, po, nullptr, D_);

    // 8) final RMS norm + 1/sqrt(2*N_LAYER)
    final_norm_kernel<<<NTOK, 256>>>(po, out);
}

// round 8
// speedup vs baseline: 3.2599x; 1.0441x over previous
#include <cuda_runtime.h>
#include <cuda_bf16.h>
#include <math.h>
#include <stdint.h>

#define B_    2
#define T_    2048
#define D_    2048
#define H_    16
#define KVH_  4
#define HD_   128
#define NTOK  (B_*T_)

// ---------------- scratch (device globals: allocation-free) ----------------
__device__ float g_q  [NTOK*D_];
__device__ float g_k  [NTOK*KVH_*HD_];
__device__ float g_v  [NTOK*KVH_*HD_];
__device__ float g_g  [NTOK*D_];
__device__ float g_o  [NTOK*D_];
// split-bf16 operands
__device__ __align__(16) __nv_bfloat16 g_ah [NTOK*D_];
__device__ __align__(16) __nv_bfloat16 g_al [NTOK*D_];
__device__ __align__(16) __nv_bfloat16 g_akh[NTOK*D_];
__device__ __align__(16) __nv_bfloat16 g_akl[NTOK*D_];
__device__ __align__(16) __nv_bfloat16 g_avh[NTOK*D_];
__device__ __align__(16) __nv_bfloat16 g_avl[NTOK*D_];
__device__ __align__(16) __nv_bfloat16 g_wth[2*D_*D_];
__device__ __align__(16) __nv_bfloat16 g_wtl[2*D_*D_];
// pre-split attention operands
__device__ __align__(16) __nv_bfloat16 g_qh [NTOK*D_];
__device__ __align__(16) __nv_bfloat16 g_ql [NTOK*D_];
__device__ __align__(16) __nv_bfloat16 g_kh [NTOK*KVH_*HD_];
__device__ __align__(16) __nv_bfloat16 g_kl [NTOK*KVH_*HD_];
__device__ __align__(16) __nv_bfloat16 g_vh [NTOK*KVH_*HD_];
__device__ __align__(16) __nv_bfloat16 g_vl [NTOK*KVH_*HD_];

// ================= baseline-ISA helpers =================
__device__ __forceinline__ uint32_t smem_u32(const void* p) {
    uint32_t a;
    asm("{ .reg .u64 t; cvta.to.shared.u64 t, %1; cvt.u32.u64 %0, t; }" : "=r"(a) : "l"(p));
    return a;
}
__device__ __forceinline__ uint32_t sw128(uint32_t off) { return off ^ ((off >> 3) & 0x70); }
__device__ __forceinline__ uint32_t sw256(uint32_t off) { return off ^ ((off >> 4) & 0x70); }

__device__ __forceinline__ void cp_async16(uint32_t dst, const void* src) {
    asm volatile("cp.async.cg.shared.global [%0], [%1], 16;" :: "r"(dst), "l"(src) : "memory");
}
#define CP_COMMIT() asm volatile("cp.async.commit_group;" ::: "memory")
#define CP_WAIT(n)  asm volatile("cp.async.wait_group %0;" :: "n"(n) : "memory")

__device__ __forceinline__ void ldsm_x4(uint32_t* r, uint32_t addr) {
    asm volatile("ldmatrix.sync.aligned.m8n8.x4.shared.b16 {%0,%1,%2,%3}, [%4];"
                 : "=r"(r[0]), "=r"(r[1]), "=r"(r[2]), "=r"(r[3]) : "r"(addr));
}
__device__ __forceinline__ void ldsm_x4_t(uint32_t* r, uint32_t addr) {
    asm volatile("ldmatrix.sync.aligned.m8n8.x4.trans.shared.b16 {%0,%1,%2,%3}, [%4];"
                 : "=r"(r[0]), "=r"(r[1]), "=r"(r[2]), "=r"(r[3]) : "r"(addr));
}
__device__ __forceinline__ void mma16816(float* d, const uint32_t* a, const uint32_t* b) {
    asm volatile("mma.sync.aligned.m16n8k16.row.col.f32.bf16.bf16.f32 "
                 "{%0,%1,%2,%3}, {%4,%5,%6,%7}, {%8,%9}, {%0,%1,%2,%3};"
                 : "+f"(d[0]), "+f"(d[1]), "+f"(d[2]), "+f"(d[3])
                 : "r"(a[0]), "r"(a[1]), "r"(a[2]), "r"(a[3]), "r"(b[0]), "r"(b[1]));
}

// fast exp on the FMA pipe
__device__ __forceinline__ float fast_exp(float x) {
    x = fmaxf(x, -80.f);
    const float LOG2E = 1.4426950408889634f;
    float t = x * LOG2E;
    float r = t + 12582912.f;
    float i = r - 12582912.f;
    float f = t - i;
    uint32_t ib = __float_as_uint(r);
    float sc = __uint_as_float((ib + 127u) << 23);
    float p = 1.3333558146e-3f;
    p = fmaf(p, f, 9.6181291076e-3f);
    p = fmaf(p, f, 5.5504108664e-2f);
    p = fmaf(p, f, 2.4022650696e-1f);
    p = fmaf(p, f, 6.9314718056e-1f);
    p = fmaf(p, f, 1.0f);
    return p * sc;
}

__device__ __forceinline__ void split2(float a, float b, uint32_t& hp, uint32_t& lp) {
    __nv_bfloat16 ha = __float2bfloat16(a), hb = __float2bfloat16(b);
    __nv_bfloat16 la = __float2bfloat16(a - __bfloat162float(ha));
    __nv_bfloat16 lb = __float2bfloat16(b - __bfloat162float(hb));
    hp = ((uint32_t)__bfloat16_as_ushort(hb) << 16) | __bfloat16_as_ushort(ha);
    lp = ((uint32_t)__bfloat16_as_ushort(lb) << 16) | __bfloat16_as_ushort(la);
}

// ================= elementwise kernels =================
__global__ void split_x_kernel(const float* __restrict__ x,
                               __nv_bfloat16* __restrict__ hi,
                               __nv_bfloat16* __restrict__ lo)
{
    int i = blockIdx.x * blockDim.x + threadIdx.x;
    float4 v = ((const float4*)x)[i];
    uint32_t h0, l0, h1, l1;
    split2(v.x, v.y, h0, l0);
    split2(v.z, v.w, h1, l1);
    ((uint2*)hi)[i] = make_uint2(h0, h1);
    ((uint2*)lo)[i] = make_uint2(l0, l1);
}

// fused time-shift mix + bf16 hi/lo split for k and v paths
__global__ void mix_split_kernel(const float* __restrict__ xk, const float* __restrict__ xv,
                                 const float* __restrict__ mk, const float* __restrict__ mv,
                                 __nv_bfloat16* __restrict__ kh, __nv_bfloat16* __restrict__ kl,
                                 __nv_bfloat16* __restrict__ vh, __nv_bfloat16* __restrict__ vl)
{
    const int D4 = D_ / 4;
    int idx = blockIdx.x * blockDim.x + threadIdx.x;
    int d4  = idx & (D4 - 1);
    int tok = idx >> 9;
    int t   = tok & (T_ - 1);

    float4 kc = ((const float4*)xk)[idx];
    float4 vc = ((const float4*)xv)[idx];
    float4 m1 = ((const float4*)mk)[d4];
    float4 m2 = ((const float4*)mv)[d4];
    float4 kp = make_float4(0.f,0.f,0.f,0.f);
    float4 vp = make_float4(0.f,0.f,0.f,0.f);
    if (t > 0) {
        kp = ((const float4*)xk)[idx - D4];
        vp = ((const float4*)xv)[idx - D4];
    }
    float4 r1, r2;
    r1.x = kc.x + m1.x*(kp.x-kc.x);  r1.y = kc.y + m1.y*(kp.y-kc.y);
    r1.z = kc.z + m1.z*(kp.z-kc.z);  r1.w = kc.w + m1.w*(kp.w-kc.w);
    r2.x = vc.x + m2.x*(vp.x-vc.x);  r2.y = vc.y + m2.y*(vp.y-vc.y);
    r2.z = vc.z + m2.z*(vp.z-vc.z);  r2.w = vc.w + m2.w*(vp.w-vc.w);

    uint32_t h0, l0, h1, l1;
    split2(r1.x, r1.y, h0, l0);  split2(r1.z, r1.w, h1, l1);
    ((uint2*)kh)[idx] = make_uint2(h0, h1);
    ((uint2*)kl)[idx] = make_uint2(l0, l1);
    split2(r2.x, r2.y, h0, l0);  split2(r2.z, r2.w, h1, l1);
    ((uint2*)vh)[idx] = make_uint2(h0, h1);
    ((uint2*)vl)[idx] = make_uint2(l0, l1);
}

__global__ void wsplit_t_kernel(const float* __restrict__ W,
                                __nv_bfloat16* __restrict__ th,
                                __nv_bfloat16* __restrict__ tl, int N)
{
    __shared__ float s[32][33];
    const int k0 = blockIdx.y * 32, n0 = blockIdx.x * 32;
    const int tx = threadIdx.x, ty = threadIdx.y;
    s[ty][tx] = W[(size_t)(k0 + ty) * N + n0 + tx];
    __syncthreads();
    float v = s[tx][ty];
    __nv_bfloat16 h = __float2bfloat16(v);
    __nv_bfloat16 l = __float2bfloat16(v - __bfloat162float(h));
    size_t o = (size_t)(n0 + ty) * D_ + k0 + tx;
    th[o] = h;
    tl[o] = l;
}

// ================= split-bf16 GEMM via mma.sync (term-major issue) =========
#define GK        2048
#define NCH       (GK/64)
#define TILEB     16384
#define STAGEB    (4*TILEB)
#define GEMM_SMEM (3*STAGEB + 1024)

__global__ void __launch_bounds__(256, 1) gemm_mma_kernel(
    const __nv_bfloat16* __restrict__ ah, const __nv_bfloat16* __restrict__ al,
    const __nv_bfloat16* __restrict__ wth, const __nv_bfloat16* __restrict__ wtl,
    float* __restrict__ C0, float* __restrict__ C1, int cstride)
{
    extern __shared__ char sm[];
    const uint32_t smb   = smem_u32(sm);
    const uint32_t tiles = (smb + 1023u) & ~1023u;

    const int tid  = threadIdx.x;
    const int wid  = tid >> 5, lane = tid & 31;
    const int wm   = wid & 3,  wn   = wid >> 2;
    const int m0   = blockIdx.y << 7;
    const int n0   = blockIdx.x << 7;

    const __nv_bfloat16* srcs[4] = { ah  + (size_t)m0 * GK, al  + (size_t)m0 * GK,
                                     wth + (size_t)n0 * GK, wtl + (size_t)n0 * GK };

    float acc[2][8][4];
#pragma unroll
    for (int i = 0; i < 2; i++)
#pragma unroll
        for (int j = 0; j < 8; j++)
#pragma unroll
            for (int q = 0; q < 4; q++) acc[i][j][q] = 0.f;

    auto prefetch = [&](int ch) {
        const uint32_t stage = tiles + (uint32_t)(ch % 3) * STAGEB;
        const int ke = ch << 6;
#pragma unroll
        for (int t = 0; t < 4; t++) {
            const __nv_bfloat16* s = srcs[t];
#pragma unroll
            for (int j = 0; j < 4; j++) {
                int idx = tid + (j << 8);
                int r   = idx >> 3;
                int c   = idx & 7;
                cp_async16(stage + t * TILEB + sw128((r << 7) + (c << 4)),
                           s + (size_t)r * GK + ke + (c << 3));
            }
        }
        CP_COMMIT();
    };

    prefetch(0);
    prefetch(1);

    for (int ch = 0; ch < NCH; ch++) {
        if (ch + 2 < NCH)      { prefetch(ch + 2); CP_WAIT(2); }
        else if (ch + 1 < NCH) { CP_WAIT(1); }
        else                   { CP_WAIT(0); }
        __syncthreads();

        const uint32_t stage = tiles + (uint32_t)(ch % 3) * STAGEB;
        const uint32_t sAh = stage,            sAl = stage + TILEB;
        const uint32_t sBh = stage + 2*TILEB,  sBl = stage + 3*TILEB;

#pragma unroll
        for (int ks = 0; ks < 4; ks++) {
            const int kb = ks << 5;

            uint32_t ahf[2][4], alf[2][4], bhf[4][4], blf[4][4];
#pragma unroll
            for (int mt = 0; mt < 2; mt++) {
                int row = wm*32 + mt*16 + (lane & 15);
                uint32_t off = sw128((uint32_t)(row << 7) + kb + ((lane >> 4) << 4));
                ldsm_x4(ahf[mt], sAh + off);
                ldsm_x4(alf[mt], sAl + off);
            }
            const int brow4 = wn*64 + (lane & 7) + ((lane >> 4) << 3);
            const int bko   = kb + (((lane >> 3) & 1) << 4);
#pragma unroll
            for (int np = 0; np < 4; np++) {
                uint32_t off = sw128((uint32_t)((brow4 + np*16) << 7) + bko);
                ldsm_x4(bhf[np], sBh + off);
                ldsm_x4(blf[np], sBl + off);
            }
            // pass 1: hi*hi (16 independent MMAs)
#pragma unroll
            for (int mt = 0; mt < 2; mt++)
#pragma unroll
                for (int np = 0; np < 4; np++) {
                    mma16816(acc[mt][2*np],   ahf[mt], bhf[np]);
                    mma16816(acc[mt][2*np+1], ahf[mt], bhf[np] + 2);
                }
            // pass 2: hi*lo
#pragma unroll
            for (int mt = 0; mt < 2; mt++)
#pragma unroll
                for (int np = 0; np < 4; np++) {
                    mma16816(acc[mt][2*np],   ahf[mt], blf[np]);
                    mma16816(acc[mt][2*np+1], ahf[mt], blf[np] + 2);
                }
            // pass 3: lo*hi
#pragma unroll
            for (int mt = 0; mt < 2; mt++)
#pragma unroll
                for (int np = 0; np < 4; np++) {
                    mma16816(acc[mt][2*np],   alf[mt], bhf[np]);
                    mma16816(acc[mt][2*np+1], alf[mt], bhf[np] + 2);
                }
        }
        __syncthreads();
    }

    float* C = C0;
    int nc = n0;
    if (C1 != nullptr && n0 >= cstride) { C = C1; nc = n0 - cstride; }

    const int er = lane >> 2, ec = (lane & 3) << 1;
#pragma unroll
    for (int mt = 0; mt < 2; mt++) {
        int r0 = m0 + wm*32 + mt*16 + er;
#pragma unroll
        for (int nt = 0; nt < 8; nt++) {
            int c = nc + wn*64 + nt*8 + ec;
            *(float2*)(C + (size_t)r0      * cstride + c) = make_float2(acc[mt][nt][0], acc[mt][nt][1]);
            *(float2*)(C + (size_t)(r0 + 8)* cstride + c) = make_float2(acc[mt][nt][2], acc[mt][nt][3]);
        }
    }
}

// ------- per-head RMS norm (+ optional RoPE), emits bf16 hi/lo split -------
__global__ void norm_head_split_kernel(const float* __restrict__ x, int heads,
                                       int do_rope, float scale,
                                       __nv_bfloat16* __restrict__ oh,
                                       __nv_bfloat16* __restrict__ ol)
{
    __shared__ float sbuf[4];
    __shared__ float svals[128];
    const int head = blockIdx.x % heads;
    const int tok  = blockIdx.x / heads;
    const int t    = tok % T_;
    const size_t base = (size_t)tok*heads*HD_ + head*HD_;
    const float* p = x + base;
    const int d = threadIdx.x;

    float v  = p[d];
    float ss = v*v;
#pragma unroll
    for (int o = 16; o > 0; o >>= 1) ss += __shfl_xor_sync(0xffffffffu, ss, o);
    if ((d & 31) == 0) sbuf[d >> 5] = ss;
    __syncthreads();
    float tot = sbuf[0] + sbuf[1] + sbuf[2] + sbuf[3];
    float r   = rsqrtf(tot * (1.f/HD_) + 1e-8f);
    float vn  = v * r;
    float f;

    if (do_rope) {
        svals[d] = vn;
        __syncthreads();
        int   j  = d & 63;
        float inv_freq = exp2f(-(float)j * (13.287712379549449f / 64.f));
        float ang = (float)t * inv_freq;
        float sn, cs;
        sincosf(ang, &sn, &cs);
        float partner = svals[d ^ 64];
        f = (d < 64) ? (vn*cs - partner*sn) : (vn*cs + partner*sn);
    } else {
        f = vn;
    }
    f *= scale;
    __nv_bfloat16 h = __float2bfloat16(f);
    __nv_bfloat16 l = __float2bfloat16(f - __bfloat162float(h));
    oh[base + d] = h;
    ol[base + d] = l;
}

// ================= flash attention via mma.sync (fused gate epilogue) ======
#define FQH  0
#define FQL  32768
#define FKV  65536
#define FSTG 65536
#define FLASH_SMEM (FKV + 2*FSTG)

__global__ void __launch_bounds__(256, 1) flash_mma_kernel(
    const __nv_bfloat16* __restrict__ qh, const __nv_bfloat16* __restrict__ ql,
    const __nv_bfloat16* __restrict__ kh, const __nv_bfloat16* __restrict__ kl,
    const __nv_bfloat16* __restrict__ vh, const __nv_bfloat16* __restrict__ vl,
    const float* __restrict__ g,
    __nv_bfloat16* __restrict__ oh_out, __nv_bfloat16* __restrict__ ol_out)
{
    extern __shared__ char sm[];
    const uint32_t smb = smem_u32(sm);

    const int tid  = threadIdx.x;
    const int w    = tid >> 5, lane = tid & 31;
    const int qt   = blockIdx.x;
    const int b    = blockIdx.y >> 4;
    const int h    = blockIdx.y & 15;
    const int kvh  = h >> 2;
    const int qs   = qt << 7;

    // ---- async load Q tile (128x128 bf16 hi+lo) ----
    {
        const __nv_bfloat16* qgh = qh + ((size_t)(b*T_ + qs))*D_ + h*HD_;
        const __nv_bfloat16* qgl = ql + ((size_t)(b*T_ + qs))*D_ + h*HD_;
#pragma unroll
        for (int it = 0; it < 8; it++) {
            int idx = tid + (it << 8);
            int r = idx >> 4, c = idx & 15;
            uint32_t off = sw256((r << 8) + (c << 4));
            cp_async16(smb + FQH + off, qgh + (size_t)r*D_ + (c << 3));
            cp_async16(smb + FQL + off, qgl + (size_t)r*D_ + (c << 3));
        }
        CP_COMMIT();
    }

    const __nv_bfloat16* kh_b = kh + (size_t)(b*T_)*(KVH_*HD_) + kvh*HD_;
    const __nv_bfloat16* kl_b = kl + (size_t)(b*T_)*(KVH_*HD_) + kvh*HD_;
    const __nv_bfloat16* vh_b = vh + (size_t)(b*T_)*(KVH_*HD_) + kvh*HD_;
    const __nv_bfloat16* vl_b = vl + (size_t)(b*T_)*(KVH_*HD_) + kvh*HD_;

    auto prefetch_kv = [&](int kt) {
        const uint32_t sb = smb + FKV + (uint32_t)(kt & 1)*FSTG;
        const size_t rb = (size_t)(kt << 6) * (KVH_*HD_);
        const __nv_bfloat16* ps[4] = { kh_b + rb, kl_b + rb, vh_b + rb, vl_b + rb };
#pragma unroll
        for (int t = 0; t < 4; t++) {
#pragma unroll
            for (int it = 0; it < 4; it++) {
                int idx = tid + (it << 8);
                int r = idx >> 4, c = idx & 15;
                cp_async16(sb + t*16384 + sw256((r << 8) + (c << 4)),
                           ps[t] + (size_t)r*(KVH_*HD_) + (c << 3));
            }
        }
        CP_COMMIT();
    };

    prefetch_kv(0);

    float o[16][4];
#pragma unroll
    for (int nh = 0; nh < 16; nh++)
#pragma unroll
        for (int qq = 0; qq < 4; qq++) o[nh][qq] = 0.f;
    float m0 = -1e30f, m1 = -1e30f, l0 = 0.f, l1 = 0.f;

    const int nkv = 2*qt + 2;
    for (int kt = 0; kt < nkv; kt++) {
        const int ks = kt << 6;
        if (kt + 1 < nkv) { prefetch_kv(kt + 1); CP_WAIT(1); }
        else              { CP_WAIT(0); }
        __syncthreads();

        const uint32_t sb  = smb + FKV + (uint32_t)(kt & 1)*FSTG;
        const uint32_t sKH = sb, sKL = sb + 16384, sVH = sb + 32768, sVL = sb + 49152;

        // ---- S = Q K^T (term-major) ----
        float s[8][4];
#pragma unroll
        for (int nt = 0; nt < 8; nt++)
#pragma unroll
            for (int qq = 0; qq < 4; qq++) s[nt][qq] = 0.f;

#pragma unroll
        for (int ks8 = 0; ks8 < 8; ks8++) {
            const int kb = ks8 << 5;
            uint32_t aQh[4], aQl[4], bhf[4][4], blf[4][4];
            {
                int row = (w << 4) + (lane & 15);
                uint32_t off = sw256((uint32_t)(row << 8) + kb + ((lane >> 4) << 4));
                ldsm_x4(aQh, smb + FQH + off);
                ldsm_x4(aQl, smb + FQL + off);
            }
            const int brow4 = (lane & 7) + ((lane >> 4) << 3);
            const int bko   = kb + (((lane >> 3) & 1) << 4);
#pragma unroll
            for (int np = 0; np < 4; np++) {
                uint32_t off = sw256((uint32_t)((brow4 + np*16) << 8) + bko);
                ldsm_x4(bhf[np], sKH + off);
                ldsm_x4(blf[np], sKL + off);
            }
#pragma unroll
            for (int np = 0; np < 4; np++) {
                mma16816(s[2*np],   aQh, bhf[np]);
                mma16816(s[2*np+1], aQh, bhf[np] + 2);
            }
#pragma unroll
            for (int np = 0; np < 4; np++) {
                mma16816(s[2*np],   aQh, blf[np]);
                mma16816(s[2*np+1], aQh, blf[np] + 2);
            }
#pragma unroll
            for (int np = 0; np < 4; np++) {
                mma16816(s[2*np],   aQl, bhf[np]);
                mma16816(s[2*np+1], aQl, bhf[np] + 2);
            }
        }

        // ---- causal mask ----
        if (kt >= 2*qt) {
            const int gr0 = qs + (w << 4) + (lane >> 2);
            const int gc0 = ks + ((lane & 3) << 1);
#pragma unroll
            for (int nt = 0; nt < 8; nt++) {
                int c = gc0 + nt*8;
                if (c     > gr0)     s[nt][0] = -1e30f;
                if (c + 1 > gr0)     s[nt][1] = -1e30f;
                if (c     > gr0 + 8) s[nt][2] = -1e30f;
                if (c + 1 > gr0 + 8) s[nt][3] = -1e30f;
            }
        }

        // ---- online softmax ----
        float mx0 = -1e30f, mx1 = -1e30f;
#pragma unroll
        for (int nt = 0; nt < 8; nt++) {
            mx0 = fmaxf(mx0, fmaxf(s[nt][0], s[nt][1]));
            mx1 = fmaxf(mx1, fmaxf(s[nt][2], s[nt][3]));
        }
        mx0 = fmaxf(mx0, __shfl_xor_sync(0xffffffffu, mx0, 1));
        mx0 = fmaxf(mx0, __shfl_xor_sync(0xffffffffu, mx0, 2));
        mx1 = fmaxf(mx1, __shfl_xor_sync(0xffffffffu, mx1, 1));
        mx1 = fmaxf(mx1, __shfl_xor_sync(0xffffffffu, mx1, 2));
        float m0n = fmaxf(m0, mx0), m1n = fmaxf(m1, mx1);
        float sc0 = fast_exp(m0 - m0n), sc1 = fast_exp(m1 - m1n);
        m0 = m0n; m1 = m1n;

        float sum0 = 0.f, sum1 = 0.f;
#pragma unroll
        for (int nt = 0; nt < 8; nt++) {
            s[nt][0] = fast_exp(s[nt][0] - m0n); sum0 += s[nt][0];
            s[nt][1] = fast_exp(s[nt][1] - m0n); sum0 += s[nt][1];
            s[nt][2] = fast_exp(s[nt][2] - m1n); sum1 += s[nt][2];
            s[nt][3] = fast_exp(s[nt][3] - m1n); sum1 += s[nt][3];
        }
        sum0 += __shfl_xor_sync(0xffffffffu, sum0, 1);
        sum0 += __shfl_xor_sync(0xffffffffu, sum0, 2);
        sum1 += __shfl_xor_sync(0xffffffffu, sum1, 1);
        sum1 += __shfl_xor_sync(0xffffffffu, sum1, 2);
        l0 = l0*sc0 + sum0;
        l1 = l1*sc1 + sum1;

#pragma unroll
        for (int nh = 0; nh < 16; nh++) {
            o[nh][0] *= sc0; o[nh][1] *= sc0;
            o[nh][2] *= sc1; o[nh][3] *= sc1;
        }

        // ---- O += P V (term-major over nhp pairs) ----
#pragma unroll
        for (int j = 0; j < 4; j++) {
            uint32_t aPh[4], aPl[4];
            split2(s[2*j][0],   s[2*j][1],   aPh[0], aPl[0]);
            split2(s[2*j][2],   s[2*j][3],   aPh[1], aPl[1]);
            split2(s[2*j+1][0], s[2*j+1][1], aPh[2], aPl[2]);
            split2(s[2*j+1][2], s[2*j+1][3], aPh[3], aPl[3]);
            const uint32_t vrow = (j << 4) + (lane & 15);
            const uint32_t nsel = (lane >> 4);
#pragma unroll
            for (int pp = 0; pp < 4; pp++) {
                uint32_t bh0[4], bl0[4], bh1[4], bl1[4];
                uint32_t off0 = sw256((vrow << 8) + ((4*pp     + nsel) << 4));
                uint32_t off1 = sw256((vrow << 8) + ((4*pp + 2 + nsel) << 4));
                ldsm_x4_t(bh0, sVH + off0);
                ldsm_x4_t(bl0, sVL + off0);
                ldsm_x4_t(bh1, sVH + off1);
                ldsm_x4_t(bl1, sVL + off1);
                // pass hi
                mma16816(o[4*pp],   aPh, bh0);
                mma16816(o[4*pp+1], aPh, bh0 + 2);
                mma16816(o[4*pp+2], aPh, bh1);
                mma16816(o[4*pp+3], aPh, bh1 + 2);
                // pass lo-P
                mma16816(o[4*pp],   aPl, bh0);
                mma16816(o[4*pp+1], aPl, bh0 + 2);
                mma16816(o[4*pp+2], aPl, bh1);
                mma16816(o[4*pp+3], aPl, bh1 + 2);
                // pass lo-V
                mma16816(o[4*pp],   aPh, bl0);
                mma16816(o[4*pp+1], aPh, bl0 + 2);
                mma16816(o[4*pp+2], aPh, bl1);
                mma16816(o[4*pp+3], aPh, bl1 + 2);
            }
        }
        __syncthreads();
    }

    // ---- fused epilogue: 1/l, per-head L2 norm, gate, split-bf16 out ----
    const float inv0 = 1.f / l0, inv1 = 1.f / l1;
    float y0[16][2], y1[16][2];
    float ss0 = 0.f, ss1 = 0.f;
#pragma unroll
    for (int nh = 0; nh < 16; nh++) {
        y0[nh][0] = o[nh][0]*inv0;  y0[nh][1] = o[nh][1]*inv0;
        y1[nh][0] = o[nh][2]*inv1;  y1[nh][1] = o[nh][3]*inv1;
        ss0 += y0[nh][0]*y0[nh][0] + y0[nh][1]*y0[nh][1];
        ss1 += y1[nh][0]*y1[nh][0] + y1[nh][1]*y1[nh][1];
    }
    ss0 += __shfl_xor_sync(0xffffffffu, ss0, 1);
    ss0 += __shfl_xor_sync(0xffffffffu, ss0, 2);
    ss1 += __shfl_xor_sync(0xffffffffu, ss1, 1);
    ss1 += __shfl_xor_sync(0xffffffffu, ss1, 2);
    const float s0 = 1.f / fmaxf(sqrtf(ss0), 1e-12f);
    const float s1 = 1.f / fmaxf(sqrtf(ss1), 1e-12f);

    const int r0 = qs + (w << 4) + (lane >> 2);
    const size_t base0 = ((size_t)(b*T_) + r0)*D_ + h*HD_ + ((lane & 3) << 1);
    const size_t base1 = base0 + (size_t)8*D_;
#pragma unroll
    for (int nh = 0; nh < 16; nh++) {
        float2 gv0 = *(const float2*)(g + base0 + nh*8);
        float2 gv1 = *(const float2*)(g + base1 + nh*8);
        uint32_t hp, lp;
        split2(gv0.x*y0[nh][0]*s0, gv0.y*y0[nh][1]*s0, hp, lp);
        *(uint32_t*)(oh_out + base0 + nh*8) = hp;
        *(uint32_t*)(ol_out + base0 + nh*8) = lp;
        split2(gv1.x*y1[nh][0]*s1, gv1.y*y1[nh][1]*s1, hp, lp);
        *(uint32_t*)(oh_out + base1 + nh*8) = hp;
        *(uint32_t*)(ol_out + base1 + nh*8) = lp;
    }
}

// ---------------- final RMS norm over D, scaled by 1/sqrt(48) ----------------
__global__ void final_norm_kernel(const float* __restrict__ in, float* __restrict__ out)
{
    __shared__ float sbuf[8];
    const int tok = blockIdx.x;
    const float* p = in + (size_t)tok*D_;
    const int base = threadIdx.x * 8;

    float4 a = *(const float4*)(p + base);
    float4 b = *(const float4*)(p + base + 4);
    float ss = a.x*a.x + a.y*a.y + a.z*a.z + a.w*a.w
             + b.x*b.x + b.y*b.y + b.z*b.z + b.w*b.w;
#pragma unroll
    for (int o = 16; o > 0; o >>= 1) ss += __shfl_xor_sync(0xffffffffu, ss, o);
    if ((threadIdx.x & 31) == 0) sbuf[threadIdx.x >> 5] = ss;
    __syncthreads();
    float tot = 0.f;
#pragma unroll
    for (int i = 0; i < 8; i++) tot += sbuf[i];
    float r = rsqrtf(tot * (1.f/D_) + 1e-8f) * 0.14433756729740643f;

    float* q = out + (size_t)tok*D_;
    a.x*=r; a.y*=r; a.z*=r; a.w*=r;
    b.x*=r; b.y*=r; b.z*=r; b.w*=r;
    *(float4*)(q + base)     = a;
    *(float4*)(q + base + 4) = b;
}

// ---------------- launcher ----------------
extern "C" void kernel_launch(void* const* d_in, const int* in_sizes, int n_in,
                              void* d_out, int out_size)
{
    (void)in_sizes; (void)n_in; (void)out_size;
    const float* xq = (const float*)d_in[0];
    const float* xk = (const float*)d_in[1];
    const float* xv = (const float*)d_in[2];
    const float* Wq = (const float*)d_in[3];
    const float* Wk = (const float*)d_in[4];
    const float* Wv = (const float*)d_in[5];
    const float* Wg = (const float*)d_in[6];
    const float* Wo = (const float*)d_in[7];
    const float* mk = (const float*)d_in[8];
    const float* mv = (const float*)d_in[9];
    float* out = (float*)d_out;

    float *pq, *pk, *pv, *pg, *po;
    __nv_bfloat16 *pah, *pal, *pakh, *pakl, *pavh, *pavl, *pwth, *pwtl;
    __nv_bfloat16 *pqh, *pql, *pkh, *pkl, *pvh, *pvl;
    cudaGetSymbolAddress((void**)&pq,   g_q);
    cudaGetSymbolAddress((void**)&pk,   g_k);
    cudaGetSymbolAddress((void**)&pv,   g_v);
    cudaGetSymbolAddress((void**)&pg,   g_g);
    cudaGetSymbolAddress((void**)&po,   g_o);
    cudaGetSymbolAddress((void**)&pah,  g_ah);
    cudaGetSymbolAddress((void**)&pal,  g_al);
    cudaGetSymbolAddress((void**)&pakh, g_akh);
    cudaGetSymbolAddress((void**)&pakl, g_akl);
    cudaGetSymbolAddress((void**)&pavh, g_avh);
    cudaGetSymbolAddress((void**)&pavl, g_avl);
    cudaGetSymbolAddress((void**)&pwth, g_wth);
    cudaGetSymbolAddress((void**)&pwtl, g_wtl);
    cudaGetSymbolAddress((void**)&pqh,  g_qh);
    cudaGetSymbolAddress((void**)&pql,  g_ql);
    cudaGetSymbolAddress((void**)&pkh,  g_kh);
    cudaGetSymbolAddress((void**)&pkl,  g_kl);
    cudaGetSymbolAddress((void**)&pvh,  g_vh);
    cudaGetSymbolAddress((void**)&pvl,  g_vl);

    cudaFuncSetAttribute(gemm_mma_kernel, cudaFuncAttributeMaxDynamicSharedMemorySize,
                         GEMM_SMEM);
    cudaFuncSetAttribute(flash_mma_kernel, cudaFuncAttributeMaxDynamicSharedMemorySize,
                         FLASH_SMEM);

    const int XS_GRID = (NTOK*D_/4)/256;
    dim3 wgrid_full(D_/32, D_/32), wgrid_kv(512/32, D_/32), wblk(32, 32);

    // 1) fused time-shift mix + split for k/v paths
    mix_split_kernel<<<XS_GRID, 256>>>(xk, xv, mk, mv, pakh, pakl, pavh, pavl);

    // 2) q-side projections: merged N=4096 GEMM (Wq | Wg)
    split_x_kernel<<<XS_GRID, 256>>>(xq, pah, pal);
    wsplit_t_kernel<<<wgrid_full, wblk>>>(Wq, pwth, pwtl, D_);
    wsplit_t_kernel<<<wgrid_full, wblk>>>(Wg, pwth + (size_t)D_*D_, pwtl + (size_t)D_*D_, D_);
    gemm_mma_kernel<<<dim3(4096/128, NTOK/128), 256, GEMM_SMEM>>>(
        pah, pal, pwth, pwtl, pq, pg, D_);

    // 3) k/v projections
    wsplit_t_kernel<<<wgrid_kv, wblk>>>(Wk, pwth, pwtl, 512);
    gemm_mma_kernel<<<dim3(512/128, NTOK/128), 256, GEMM_SMEM>>>(
        pakh, pakl, pwth, pwtl, pk, nullptr, 512);
    wsplit_t_kernel<<<wgrid_kv, wblk>>>(Wv, pwth, pwtl, 512);
    gemm_mma_kernel<<<dim3(512/128, NTOK/128), 256, GEMM_SMEM>>>(
        pavh, pavl, pwth, pwtl, pv, nullptr, 512);

    // 4) per-head RMS norm (+RoPE for q,k) with bf16 hi/lo split output
    norm_head_split_kernel<<<NTOK*H_,   128>>>(pq, H_,   1, 0.08838834764831845f, pqh, pql);
    norm_head_split_kernel<<<NTOK*KVH_, 128>>>(pk, KVH_, 1, 1.f, pkh, pkl);
    norm_head_split_kernel<<<NTOK*KVH_, 128>>>(pv, KVH_, 0, 1.f, pvh, pvl);

    // 5) causal GQA attention + fused L2-norm/gate/split epilogue
    flash_mma_kernel<<<dim3(T_/128, B_*H_), 256, FLASH_SMEM>>>(
        pqh, pql, pkh, pkl, pvh, pvl, pg, pah, pal);

    // 6) output projection
    wsplit_t_kernel<<<wgrid_full, wblk>>>(Wo, pwth, pwtl, D_);
    gemm_mma_kernel<<<dim3(D_/128, NTOK/128), 256, GEMM_SMEM>>>(
        pah, pal, pwth, pwtl, po, nullptr, D_);

    // 7) final RMS norm + 1/sqrt(2*N_LAYER)
    final_norm_kernel<<<NTOK, 256>>>(po, out);
}